// round 4
// baseline (speedup 1.0000x reference)
#include <cuda_runtime.h>
#include <cuda_bf16.h>
#include <math.h>

// ---------------- problem constants ----------------
#define CB 8       // batch
#define CT 128     // time
#define CE 512     // embed dim
#define CH 1024    // hidden
#define CM 512     // mem hidden
#define CM2 1024   // 2*M
#define CS 16
#define CU 128
#define CW 1024
#define CV 32000
#define C3H 3072
#define CF 2048    // H + 2M (feature dim into output proj)

// ---------------- scratch (device globals; no runtime alloc) ----------------
__device__ float g_emb[CB * CT * CE];          // 2 MB
__device__ float g_gi[CB * CT * C3H];          // 12.6 MB (reused for both layers)
__device__ float g_h1[CB * CT * CH];           // 4 MB
__device__ float g_rnn[CB * CT * CH];          // 4 MB
__device__ float g_hbuf[2 * CB * CH];          // GRU state double buffer
__device__ float g_proj_s[CB * CS * CH];
__device__ float g_proj_u[CB * CU * CH];
__device__ float g_proj_w[CB * CW * CH];       // 33.5 MB
__device__ float g_sc_s[CB * CT * CS];
__device__ float g_sc_u[CB * CT * CU];
__device__ float g_sc_w[CB * CT * CW];
__device__ float g_suw[CB * CT * CW];          // 4 MB
__device__ float g_wT[CB * CM2 * CW];          // 33.5 MB  (w_output transposed per batch)
__device__ float g_feat[CB * CT * CF];         // 8.4 MB
__device__ unsigned g_bar_arr = 0;
__device__ unsigned g_bar_gen = 0;

// ---------------- grid barrier (persistent GRU kernel) ----------------
__device__ __forceinline__ void grid_sync_all(unsigned nb) {
    __threadfence();
    __syncthreads();
    if (threadIdx.x == 0) {
        unsigned gen = atomicAdd(&g_bar_gen, 0u);
        if (atomicAdd(&g_bar_arr, 1u) == nb - 1u) {
            atomicExch(&g_bar_arr, 0u);
            __threadfence();
            atomicAdd(&g_bar_gen, 1u);
        } else {
            while (atomicAdd(&g_bar_gen, 0u) == gen) { __nanosleep(64); }
        }
    }
    __syncthreads();
}

// ---------------- block reductions (256 threads fixed) ----------------
__device__ __forceinline__ float blockReduceMax256(float v, float* red) {
    #pragma unroll
    for (int o = 16; o; o >>= 1) v = fmaxf(v, __shfl_xor_sync(0xffffffffu, v, o));
    if ((threadIdx.x & 31) == 0) red[threadIdx.x >> 5] = v;
    __syncthreads();
    if (threadIdx.x < 32) {
        float r = (threadIdx.x < 8) ? red[threadIdx.x] : -INFINITY;
        #pragma unroll
        for (int o = 4; o; o >>= 1) r = fmaxf(r, __shfl_xor_sync(0xffffffffu, r, o));
        if (threadIdx.x == 0) red[0] = r;
    }
    __syncthreads();
    float out = red[0];
    __syncthreads();
    return out;
}

__device__ __forceinline__ float blockReduceSum256(float v, float* red) {
    #pragma unroll
    for (int o = 16; o; o >>= 1) v += __shfl_xor_sync(0xffffffffu, v, o);
    if ((threadIdx.x & 31) == 0) red[threadIdx.x >> 5] = v;
    __syncthreads();
    if (threadIdx.x < 32) {
        float r = (threadIdx.x < 8) ? red[threadIdx.x] : 0.f;
        #pragma unroll
        for (int o = 4; o; o >>= 1) r += __shfl_xor_sync(0xffffffffu, r, o);
        if (threadIdx.x == 0) red[0] = r;
    }
    __syncthreads();
    float out = red[0];
    __syncthreads();
    return out;
}

// ---------------- embedding gather ----------------
__global__ void embed_kernel(const int* __restrict__ target, const float* __restrict__ emb) {
    int i = blockIdx.x * blockDim.x + threadIdx.x;
    if (i < CB * CT * CE) {
        int bt = i / CE, e = i - bt * CE;
        g_emb[i] = emb[(size_t)target[bt] * CE + e];
    }
}

// ---------------- generic NT GEMM: C[m,n] = A[m,:] . B[n,:] + bias[n] ----------------
// Requires M%128==0, N%128==0, K%8==0 (all call sites satisfy this).
__global__ __launch_bounds__(256) void sgemm_nt(
    const float* __restrict__ A, const float* __restrict__ Bm,
    const float* __restrict__ bias, float* __restrict__ C,
    int M, int N, int K, int ldc,
    long sA, long sB, long sC)
{
    __shared__ float As[8][128];
    __shared__ float Bs[8][128];
    const float* Ab = A + (size_t)blockIdx.z * sA;
    const float* Bb = Bm + (size_t)blockIdx.z * sB;
    float* Cb = C + (size_t)blockIdx.z * sC;
    int n0 = blockIdx.x * 128, m0 = blockIdx.y * 128;
    int tid = threadIdx.x;
    int arow = tid >> 1, acol = (tid & 1) * 4;
    int ty = tid >> 4, tx = tid & 15;
    float acc[8][8];
    #pragma unroll
    for (int i = 0; i < 8; i++)
        #pragma unroll
        for (int j = 0; j < 8; j++) acc[i][j] = 0.f;

    for (int k0 = 0; k0 < K; k0 += 8) {
        float4 av = *(const float4*)(Ab + (size_t)(m0 + arow) * K + k0 + acol);
        float4 bv = *(const float4*)(Bb + (size_t)(n0 + arow) * K + k0 + acol);
        As[acol + 0][arow] = av.x; As[acol + 1][arow] = av.y;
        As[acol + 2][arow] = av.z; As[acol + 3][arow] = av.w;
        Bs[acol + 0][arow] = bv.x; Bs[acol + 1][arow] = bv.y;
        Bs[acol + 2][arow] = bv.z; Bs[acol + 3][arow] = bv.w;
        __syncthreads();
        #pragma unroll
        for (int kk = 0; kk < 8; kk++) {
            float a[8], b[8];
            #pragma unroll
            for (int i = 0; i < 8; i++) a[i] = As[kk][ty * 8 + i];
            #pragma unroll
            for (int j = 0; j < 8; j++) b[j] = Bs[kk][tx * 8 + j];
            #pragma unroll
            for (int i = 0; i < 8; i++)
                #pragma unroll
                for (int j = 0; j < 8; j++) acc[i][j] += a[i] * b[j];
        }
        __syncthreads();
    }
    #pragma unroll
    for (int i = 0; i < 8; i++) {
        int m = m0 + ty * 8 + i;
        #pragma unroll
        for (int j = 0; j < 8; j++) {
            int n = n0 + tx * 8 + j;
            float v = acc[i][j] + (bias ? bias[n] : 0.f);
            Cb[(size_t)m * ldc + n] = v;
        }
    }
}

// ---------------- persistent GRU layer ----------------
// gi: [B*T, 3H] precomputed x@Wi^T + bi ; Wh: [3H, H]; bh: [3H]; hout: [B,T,H]
__global__ __launch_bounds__(256) void gru_layer_kernel(
    const float* __restrict__ gi, const float* __restrict__ Wh,
    const float* __restrict__ bh, float* __restrict__ hout)
{
    __shared__ float h_s[CB * CH];   // 32 KB
    int tid = threadIdx.x;
    // zero hidden state (both buffers)
    for (int i = tid + blockIdx.x * 256; i < 2 * CB * CH; i += gridDim.x * 256)
        g_hbuf[i] = 0.f;
    grid_sync_all(gridDim.x);

    int warp = tid >> 5, lane = tid & 31;
    int j = blockIdx.x * 8 + warp;                 // this warp's hidden unit
    float bhr = bh[0 * CH + j], bhz = bh[1 * CH + j], bhn = bh[2 * CH + j];
    const float* Wr = Wh + (size_t)(0 * CH + j) * CH;
    const float* Wz = Wh + (size_t)(1 * CH + j) * CH;
    const float* Wn = Wh + (size_t)(2 * CH + j) * CH;

    for (int t = 0; t < CT; t++) {
        int cur = t & 1;
        const float* hsrc = g_hbuf + cur * CB * CH;
        for (int i = tid; i < CB * CH / 4; i += 256)
            ((float4*)h_s)[i] = ((const float4*)hsrc)[i];
        __syncthreads();

        float accr[CB], accz[CB], accn[CB];
        #pragma unroll
        for (int b = 0; b < CB; b++) { accr[b] = 0.f; accz[b] = 0.f; accn[b] = 0.f; }
        for (int k = lane * 4; k < CH; k += 128) {
            float4 wr = *(const float4*)(Wr + k);
            float4 wz = *(const float4*)(Wz + k);
            float4 wn = *(const float4*)(Wn + k);
            #pragma unroll
            for (int b = 0; b < CB; b++) {
                float4 hv = *(const float4*)(h_s + b * CH + k);
                accr[b] += wr.x * hv.x + wr.y * hv.y + wr.z * hv.z + wr.w * hv.w;
                accz[b] += wz.x * hv.x + wz.y * hv.y + wz.z * hv.z + wz.w * hv.w;
                accn[b] += wn.x * hv.x + wn.y * hv.y + wn.z * hv.z + wn.w * hv.w;
            }
        }
        #pragma unroll
        for (int b = 0; b < CB; b++) {
            #pragma unroll
            for (int o = 16; o; o >>= 1) {
                accr[b] += __shfl_xor_sync(0xffffffffu, accr[b], o);
                accz[b] += __shfl_xor_sync(0xffffffffu, accz[b], o);
                accn[b] += __shfl_xor_sync(0xffffffffu, accn[b], o);
            }
        }
        if (lane == 0) {
            #pragma unroll
            for (int b = 0; b < CB; b++) {
                const float* gib = gi + (size_t)(b * CT + t) * C3H;
                float ir = gib[0 * CH + j], iz = gib[1 * CH + j], inn = gib[2 * CH + j];
                float hprev = h_s[b * CH + j];
                float r = 1.f / (1.f + expf(-(ir + accr[b] + bhr)));
                float z = 1.f / (1.f + expf(-(iz + accz[b] + bhz)));
                float n = tanhf(inn + r * (accn[b] + bhn));
                float hn = (1.f - z) * n + z * hprev;
                g_hbuf[(cur ^ 1) * CB * CH + b * CH + j] = hn;
                hout[(size_t)(b * CT + t) * CH + j] = hn;
            }
        }
        grid_sync_all(gridDim.x);
    }
}

// ---------------- small attention scores (one warp per dot), N in {16,128} ----------------
__global__ void attn_scores_kernel(const float* __restrict__ q, const float* __restrict__ proj,
                                   float* __restrict__ out, int N) {
    int gw = (blockIdx.x * blockDim.x + threadIdx.x) >> 5;
    int lane = threadIdx.x & 31;
    if (gw >= CB * CT * N) return;
    int n = gw % N;
    int bt = gw / N;
    int b = bt / CT;
    const float* qp = q + (size_t)bt * CH;
    const float* pp = proj + (size_t)(b * N + n) * CH;
    float acc = 0.f;
    for (int k = lane * 4; k < CH; k += 128) {
        float4 qa = *(const float4*)(qp + k);
        float4 pa = *(const float4*)(pp + k);
        acc += qa.x * pa.x + qa.y * pa.y + qa.z * pa.z + qa.w * pa.w;
    }
    #pragma unroll
    for (int o = 16; o; o >>= 1) acc += __shfl_xor_sync(0xffffffffu, acc, o);
    if (lane == 0) out[gw] = acc;
}

// ---------------- fused masked softmaxes + hierarchical combine + final softmax ----------------
__global__ __launch_bounds__(256) void combine_kernel(
    const int* __restrict__ s_len, const int* __restrict__ u_len, const int* __restrict__ w_len,
    const int* __restrict__ seg, const int* __restrict__ utt)
{
    int bt = blockIdx.x, b = bt / CT, tid = threadIdx.x;
    __shared__ float ss[CS];
    __shared__ float su[CU];
    __shared__ float sw[CW];
    __shared__ float red[32];
    int sl = s_len[b], ul = u_len[b], wl = w_len[b];

    // segment softmax (warp 0)
    if (tid < 32) {
        float v = (tid < sl) ? g_sc_s[bt * CS + tid] : -INFINITY;
        float m = v;
        #pragma unroll
        for (int o = 16; o; o >>= 1) m = fmaxf(m, __shfl_xor_sync(0xffffffffu, m, o));
        float e = (tid < sl) ? expf(v - m) : 0.f;
        float s = e;
        #pragma unroll
        for (int o = 16; o; o >>= 1) s += __shfl_xor_sync(0xffffffffu, s, o);
        if (tid < CS) ss[tid] = e / s;
    }
    // utterance softmax
    float uv = (tid < CU && tid < ul) ? g_sc_u[bt * CU + tid] : -INFINITY;
    float um = blockReduceMax256(uv, red);
    float ue = (tid < CU && tid < ul) ? expf(uv - um) : 0.f;
    float us = blockReduceSum256(ue, red);
    if (tid < CU) su[tid] = ue / us;
    // word softmax
    float wv[4], we[4];
    float wm = -INFINITY;
    #pragma unroll
    for (int i = 0; i < 4; i++) {
        int idx = tid + 256 * i;
        wv[i] = (idx < wl) ? g_sc_w[(size_t)bt * CW + idx] : -INFINITY;
        wm = fmaxf(wm, wv[i]);
    }
    wm = blockReduceMax256(wm, red);
    float wsum = 0.f;
    #pragma unroll
    for (int i = 0; i < 4; i++) {
        int idx = tid + 256 * i;
        we[i] = (idx < wl) ? expf(wv[i] - wm) : 0.f;
        wsum += we[i];
    }
    wsum = blockReduceSum256(wsum, red);
    #pragma unroll
    for (int i = 0; i < 4; i++) sw[tid + 256 * i] = we[i] / wsum;
    __syncthreads();
    // seg->utt product
    if (tid < CU) {
        float v2 = (tid < ul) ? ss[seg[b * CU + tid]] * su[tid] : 0.f;
        su[tid] = v2;
    }
    __syncthreads();
    // utt->word product (zeros for invalid), then softmax over FULL W axis
    float pv[4];
    #pragma unroll
    for (int i = 0; i < 4; i++) {
        int idx = tid + 256 * i;
        pv[i] = (idx < wl) ? su[utt[b * CW + idx]] * sw[idx] : 0.f;
    }
    float pm = fmaxf(fmaxf(pv[0], pv[1]), fmaxf(pv[2], pv[3]));
    pm = blockReduceMax256(pm, red);
    float pe[4];
    float psum = 0.f;
    #pragma unroll
    for (int i = 0; i < 4; i++) { pe[i] = expf(pv[i] - pm); psum += pe[i]; }
    psum = blockReduceSum256(psum, red);
    #pragma unroll
    for (int i = 0; i < 4; i++)
        g_suw[(size_t)bt * CW + tid + 256 * i] = pe[i] / psum;
}

// ---------------- per-batch transpose of w_output: [B,W,2M] -> [B,2M,W] ----------------
__global__ void transpose_w_kernel(const float* __restrict__ wo) {
    __shared__ float tile[32][33];
    int b = blockIdx.z;
    int w0 = blockIdx.x * 32, m0 = blockIdx.y * 32;
    int x = threadIdx.x, y = threadIdx.y;
    #pragma unroll
    for (int i = 0; i < 32; i += 8)
        tile[y + i][x] = wo[((size_t)b * CW + (w0 + y + i)) * CM2 + m0 + x];
    __syncthreads();
    #pragma unroll
    for (int i = 0; i < 32; i += 8)
        g_wT[((size_t)b * CM2 + (m0 + y + i)) * CW + w0 + x] = tile[x][y + i];
}

// ---------------- copy rnn_out into second half of feature matrix ----------------
__global__ void copy_rnn_kernel() {
    int i = blockIdx.x * blockDim.x + threadIdx.x;
    if (i < CB * CT * CH) {
        int bt = i / CH, j = i - bt * CH;
        g_feat[(size_t)bt * CF + CM2 + j] = g_rnn[i];
    }
}

// ---------------- in-place log_softmax over V per (b,t) row ----------------
__global__ __launch_bounds__(256) void logsoftmax_kernel(float* __restrict__ out) {
    __shared__ float red[32];
    int row = blockIdx.x, tid = threadIdx.x;
    float* p = out + (size_t)row * CV;
    float m = -INFINITY;
    for (int i = tid; i < CV; i += 256) m = fmaxf(m, p[i]);
    m = blockReduceMax256(m, red);
    float s = 0.f;
    for (int i = tid; i < CV; i += 256) s += expf(p[i] - m);
    s = blockReduceSum256(s, red);
    float lse = m + logf(s);
    for (int i = tid; i < CV; i += 256) p[i] -= lse;
}

// ---------------- launch ----------------
extern "C" void kernel_launch(void* const* d_in, const int* in_sizes, int n_in,
                              void* d_out, int out_size) {
    const int*   target   = (const int*)d_in[0];
    const float* embedding= (const float*)d_in[1];
    const float* W_ih0    = (const float*)d_in[2];
    const float* W_hh0    = (const float*)d_in[3];
    const float* b_ih0    = (const float*)d_in[4];
    const float* b_hh0    = (const float*)d_in[5];
    const float* W_ih1    = (const float*)d_in[6];
    const float* W_hh1    = (const float*)d_in[7];
    const float* b_ih1    = (const float*)d_in[8];
    const float* b_hh1    = (const float*)d_in[9];
    const float* att_s_w  = (const float*)d_in[10];
    const float* att_s_b  = (const float*)d_in[11];
    const float* att_u_w  = (const float*)d_in[12];
    const float* att_u_b  = (const float*)d_in[13];
    const float* att_w_w  = (const float*)d_in[14];
    const float* att_w_b  = (const float*)d_in[15];
    const float* out_w    = (const float*)d_in[16];
    const float* out_b    = (const float*)d_in[17];
    const float* s_output = (const float*)d_in[18];
    const float* u_output = (const float*)d_in[19];
    const float* w_output = (const float*)d_in[20];
    const int*   s_len    = (const int*)d_in[21];
    const int*   u_len    = (const int*)d_in[22];
    const int*   w_len    = (const int*)d_in[23];
    const int*   seg      = (const int*)d_in[24];
    const int*   utt      = (const int*)d_in[25];
    float* out = (float*)d_out;

    float *p_emb, *p_gi, *p_h1, *p_rnn, *p_ps, *p_pu, *p_pw, *p_scs, *p_scu, *p_scw, *p_suw, *p_wT, *p_feat;
    cudaGetSymbolAddress((void**)&p_emb, g_emb);
    cudaGetSymbolAddress((void**)&p_gi, g_gi);
    cudaGetSymbolAddress((void**)&p_h1, g_h1);
    cudaGetSymbolAddress((void**)&p_rnn, g_rnn);
    cudaGetSymbolAddress((void**)&p_ps, g_proj_s);
    cudaGetSymbolAddress((void**)&p_pu, g_proj_u);
    cudaGetSymbolAddress((void**)&p_pw, g_proj_w);
    cudaGetSymbolAddress((void**)&p_scs, g_sc_s);
    cudaGetSymbolAddress((void**)&p_scu, g_sc_u);
    cudaGetSymbolAddress((void**)&p_scw, g_sc_w);
    cudaGetSymbolAddress((void**)&p_suw, g_suw);
    cudaGetSymbolAddress((void**)&p_wT, g_wT);
    cudaGetSymbolAddress((void**)&p_feat, g_feat);

    // 1. embedding gather
    embed_kernel<<<(CB * CT * CE + 255) / 256, 256>>>(target, embedding);
    // 2. gi0 = emb @ W_ih0^T + b_ih0   [1024, 3072], K=512
    sgemm_nt<<<dim3(C3H / 128, (CB * CT) / 128, 1), 256>>>(p_emb, W_ih0, b_ih0, p_gi,
        CB * CT, C3H, CE, C3H, 0, 0, 0);
    // 3. GRU layer 0 (persistent)
    gru_layer_kernel<<<128, 256>>>(p_gi, W_hh0, b_hh0, p_h1);
    // 4. gi1 = h1 @ W_ih1^T + b_ih1    [1024, 3072], K=1024
    sgemm_nt<<<dim3(C3H / 128, (CB * CT) / 128, 1), 256>>>(p_h1, W_ih1, b_ih1, p_gi,
        CB * CT, C3H, CH, C3H, 0, 0, 0);
    // 5. GRU layer 1
    gru_layer_kernel<<<128, 256>>>(p_gi, W_hh1, b_hh1, p_rnn);
    // 6. attention memory projections
    sgemm_nt<<<dim3(CH / 128, (CB * CS) / 128, 1), 256>>>(s_output, att_s_w, att_s_b, p_ps,
        CB * CS, CH, CM, CH, 0, 0, 0);
    sgemm_nt<<<dim3(CH / 128, (CB * CU) / 128, 1), 256>>>(u_output, att_u_w, att_u_b, p_pu,
        CB * CU, CH, CM, CH, 0, 0, 0);
    sgemm_nt<<<dim3(CH / 128, (CB * CW) / 128, 1), 256>>>(w_output, att_w_w, att_w_b, p_pw,
        CB * CW, CH, CM2, CH, 0, 0, 0);
    // 7. raw scores
    attn_scores_kernel<<<(CB * CT * CS) / 8, 256>>>(p_rnn, p_ps, p_scs, CS);
    attn_scores_kernel<<<(CB * CT * CU) / 8, 256>>>(p_rnn, p_pu, p_scu, CU);
    sgemm_nt<<<dim3(CW / 128, CT / 128, CB), 256>>>(p_rnn, p_pw, nullptr, p_scw,
        CT, CW, CH, CW, (long)CT * CH, (long)CW * CH, (long)CT * CW);
    // 8. masked softmaxes + hierarchical combine + final softmax
    combine_kernel<<<CB * CT, 256>>>(s_len, u_len, w_len, seg, utt);
    // 9. context = suw @ w_output  (needs w_output^T per batch for NT gemm)
    transpose_w_kernel<<<dim3(CW / 32, CM2 / 32, CB), dim3(32, 8)>>>(w_output);
    sgemm_nt<<<dim3(CM2 / 128, CT / 128, CB), 256>>>(p_suw, p_wT, nullptr, p_feat,
        CT, CM2, CW, CF, (long)CT * CW, (long)CM2 * CW, (long)CT * CF);
    // 10. feat[:, 1024:2048] = rnn_out
    copy_rnn_kernel<<<(CB * CT * CH + 255) / 256, 256>>>();
    // 11. logits = feat @ out_w^T + out_b  -> d_out   [1024, 32000], K=2048
    sgemm_nt<<<dim3(CV / 128, (CB * CT) / 128, 1), 256>>>(p_feat, out_w, out_b, out,
        CB * CT, CV, CF, CV, 0, 0, 0);
    // 12. in-place log_softmax
    logsoftmax_kernel<<<CB * CT, 256>>>(out);
}

// round 5
// speedup vs baseline: 1.8873x; 1.8873x over previous
#include <cuda_runtime.h>
#include <cuda_bf16.h>
#include <math.h>

// ---------------- problem constants ----------------
#define CB 8       // batch
#define CT 128     // time
#define CE 512     // embed dim
#define CH 1024    // hidden
#define CM 512     // mem hidden
#define CM2 1024   // 2*M
#define CS 16
#define CU 128
#define CW 1024
#define CV 32000
#define C3H 3072
#define CF 2048    // H + 2M (feature dim into output proj)

// ---------------- scratch (device globals; no runtime alloc) ----------------
__device__ float g_emb[CB * CT * CE];
__device__ float g_gi[CB * CT * C3H];
__device__ float g_h1[CB * CT * CH];
__device__ float g_rnn[CB * CT * CH];
__device__ float g_hbuf[2 * CB * CH];
__device__ float g_proj_s[CB * CS * CH];
__device__ float g_proj_u[CB * CU * CH];
__device__ float g_proj_w[CB * CW * CH];
__device__ float g_sc_s[CB * CT * CS];
__device__ float g_sc_u[CB * CT * CU];
__device__ float g_sc_w[CB * CT * CW];
__device__ float g_suw[CB * CT * CW];
__device__ float g_wT[CB * CM2 * CW];
__device__ float g_feat[CB * CT * CF];
__device__ unsigned g_bar_arr = 0;
__device__ unsigned g_bar_gen = 0;

// ---------------- grid barrier (persistent GRU kernel) ----------------
__device__ __forceinline__ void grid_sync_all(unsigned nb) {
    __threadfence();
    __syncthreads();
    if (threadIdx.x == 0) {
        unsigned gen = atomicAdd(&g_bar_gen, 0u);
        if (atomicAdd(&g_bar_arr, 1u) == nb - 1u) {
            atomicExch(&g_bar_arr, 0u);
            __threadfence();
            atomicAdd(&g_bar_gen, 1u);
        } else {
            while (atomicAdd(&g_bar_gen, 0u) == gen) { __nanosleep(64); }
        }
    }
    __syncthreads();
}

// ---------------- block reductions (256 threads fixed) ----------------
__device__ __forceinline__ float blockReduceMax256(float v, float* red) {
    #pragma unroll
    for (int o = 16; o; o >>= 1) v = fmaxf(v, __shfl_xor_sync(0xffffffffu, v, o));
    if ((threadIdx.x & 31) == 0) red[threadIdx.x >> 5] = v;
    __syncthreads();
    if (threadIdx.x < 32) {
        float r = (threadIdx.x < 8) ? red[threadIdx.x] : -INFINITY;
        #pragma unroll
        for (int o = 4; o; o >>= 1) r = fmaxf(r, __shfl_xor_sync(0xffffffffu, r, o));
        if (threadIdx.x == 0) red[0] = r;
    }
    __syncthreads();
    float out = red[0];
    __syncthreads();
    return out;
}

__device__ __forceinline__ float blockReduceSum256(float v, float* red) {
    #pragma unroll
    for (int o = 16; o; o >>= 1) v += __shfl_xor_sync(0xffffffffu, v, o);
    if ((threadIdx.x & 31) == 0) red[threadIdx.x >> 5] = v;
    __syncthreads();
    if (threadIdx.x < 32) {
        float r = (threadIdx.x < 8) ? red[threadIdx.x] : 0.f;
        #pragma unroll
        for (int o = 4; o; o >>= 1) r += __shfl_xor_sync(0xffffffffu, r, o);
        if (threadIdx.x == 0) red[0] = r;
    }
    __syncthreads();
    float out = red[0];
    __syncthreads();
    return out;
}

// ---------------- embedding gather ----------------
__global__ void embed_kernel(const int* __restrict__ target, const float* __restrict__ emb) {
    int i = blockIdx.x * blockDim.x + threadIdx.x;
    if (i < CB * CT * CE) {
        int bt = i / CE, e = i - bt * CE;
        g_emb[i] = emb[(size_t)target[bt] * CE + e];
    }
}

// ---------------- tf32 helpers ----------------
__device__ __forceinline__ unsigned f2tf(float x) {
    unsigned r;
    asm("cvt.rna.tf32.f32 %0, %1;" : "=r"(r) : "f"(x));
    return r;
}

__device__ __forceinline__ void mma_tf32(float* d, const unsigned* a, const unsigned* b) {
    asm volatile(
        "mma.sync.aligned.m16n8k8.row.col.f32.tf32.tf32.f32 "
        "{%0,%1,%2,%3}, {%4,%5,%6,%7}, {%8,%9}, {%0,%1,%2,%3};"
        : "+f"(d[0]), "+f"(d[1]), "+f"(d[2]), "+f"(d[3])
        : "r"(a[0]), "r"(a[1]), "r"(a[2]), "r"(a[3]), "r"(b[0]), "r"(b[1]));
}

// ---------------- tf32 tensor-core NT GEMM ----------------
// C[m,n] = A[m,:] . B[n,:] + bias[n].  A:[M,K] row-major, B:[N,K] row-major.
// Requires M%128==0, N%128==0, K%32==0 (all call sites satisfy).
// Grid: (M/128, N/128, batch). Block tile 128x128, K-tile 32. 8 warps: 2(M) x 4(N),
// warp tile 64x32 via m16n8k8. Smem: k-major groups of 4 with XOR swizzle:
//   word index = kq*512 + (((row<<2)|j) ^ (kq<<2)),  row in [0,128), kq=k/4, j=k%4
// -> fragment LDS conflict-free; staging STS 4-way (acceptable, MMA-bound).
__global__ __launch_bounds__(256, 2) void tgemm_nt(
    const float* __restrict__ A, const float* __restrict__ Bm,
    const float* __restrict__ bias, float* __restrict__ C,
    int M, int N, int K, int ldc,
    long sA, long sB, long sC)
{
    __shared__ unsigned As[8 * 512];   // 16 KB
    __shared__ unsigned Bs[8 * 512];   // 16 KB
    const float* Ab = A + (size_t)blockIdx.z * sA;
    const float* Bb = Bm + (size_t)blockIdx.z * sB;
    float* Cb = C + (size_t)blockIdx.z * sC;
    int m0 = blockIdx.x * 128, n0 = blockIdx.y * 128;
    int tid = threadIdx.x;
    int warp = tid >> 5, lane = tid & 31;
    int wm = (warp >> 2) * 64;       // warp M offset (0 or 64)
    int wn = (warp & 3) * 32;        // warp N offset
    int lr = lane >> 2, lq = lane & 3;

    float acc[4][4][4];
    #pragma unroll
    for (int mi = 0; mi < 4; mi++)
        #pragma unroll
        for (int ni = 0; ni < 4; ni++)
            #pragma unroll
            for (int r = 0; r < 4; r++) acc[mi][ni][r] = 0.f;

    for (int kt = 0; kt < K; kt += 32) {
        // ---- stage A,B tiles (fp32 -> tf32) ----
        #pragma unroll
        for (int i = 0; i < 4; i++) {
            int idx = tid + 256 * i;
            int row = idx >> 3, kq = idx & 7;
            float4 av = *(const float4*)(Ab + (size_t)(m0 + row) * K + kt + kq * 4);
            float4 bv = *(const float4*)(Bb + (size_t)(n0 + row) * K + kt + kq * 4);
            unsigned base = kq * 512 + ((row << 2) ^ (kq << 2));
            As[base + 0] = f2tf(av.x); As[base + 1] = f2tf(av.y);
            As[base + 2] = f2tf(av.z); As[base + 3] = f2tf(av.w);
            Bs[base + 0] = f2tf(bv.x); Bs[base + 1] = f2tf(bv.y);
            Bs[base + 2] = f2tf(bv.z); Bs[base + 3] = f2tf(bv.w);
        }
        __syncthreads();

        // ---- compute: 4 k-steps of 8 ----
        #pragma unroll
        for (int kk = 0; kk < 4; kk++) {
            int kq0 = 2 * kk, kq1 = 2 * kk + 1;
            unsigned a[4][4], b[4][2];
            #pragma unroll
            for (int mi = 0; mi < 4; mi++) {
                int m = wm + mi * 16 + lr;
                a[mi][0] = As[kq0 * 512 + (((m << 2) | lq) ^ (kq0 << 2))];
                a[mi][1] = As[kq0 * 512 + ((((m + 8) << 2) | lq) ^ (kq0 << 2))];
                a[mi][2] = As[kq1 * 512 + (((m << 2) | lq) ^ (kq1 << 2))];
                a[mi][3] = As[kq1 * 512 + ((((m + 8) << 2) | lq) ^ (kq1 << 2))];
            }
            #pragma unroll
            for (int ni = 0; ni < 4; ni++) {
                int n = wn + ni * 8 + lr;
                b[ni][0] = Bs[kq0 * 512 + (((n << 2) | lq) ^ (kq0 << 2))];
                b[ni][1] = Bs[kq1 * 512 + (((n << 2) | lq) ^ (kq1 << 2))];
            }
            #pragma unroll
            for (int mi = 0; mi < 4; mi++)
                #pragma unroll
                for (int ni = 0; ni < 4; ni++)
                    mma_tf32(acc[mi][ni], a[mi], b[ni]);
        }
        __syncthreads();
    }

    // ---- epilogue ----
    #pragma unroll
    for (int mi = 0; mi < 4; mi++) {
        #pragma unroll
        for (int ni = 0; ni < 4; ni++) {
            int m = m0 + wm + mi * 16 + lr;
            int n = n0 + wn + ni * 8 + lq * 2;
            float b0 = bias ? bias[n] : 0.f;
            float b1 = bias ? bias[n + 1] : 0.f;
            float2 v0 = make_float2(acc[mi][ni][0] + b0, acc[mi][ni][1] + b1);
            float2 v1 = make_float2(acc[mi][ni][2] + b0, acc[mi][ni][3] + b1);
            *(float2*)(Cb + (size_t)m * ldc + n) = v0;
            *(float2*)(Cb + (size_t)(m + 8) * ldc + n) = v1;
        }
    }
}

// ---------------- persistent GRU layer ----------------
__global__ __launch_bounds__(256) void gru_layer_kernel(
    const float* __restrict__ gi, const float* __restrict__ Wh,
    const float* __restrict__ bh, float* __restrict__ hout)
{
    __shared__ float h_s[CB * CH];   // 32 KB
    int tid = threadIdx.x;
    for (int i = tid + blockIdx.x * 256; i < 2 * CB * CH; i += gridDim.x * 256)
        g_hbuf[i] = 0.f;
    grid_sync_all(gridDim.x);

    int warp = tid >> 5, lane = tid & 31;
    int j = blockIdx.x * 8 + warp;
    float bhr = bh[0 * CH + j], bhz = bh[1 * CH + j], bhn = bh[2 * CH + j];
    const float* Wr = Wh + (size_t)(0 * CH + j) * CH;
    const float* Wz = Wh + (size_t)(1 * CH + j) * CH;
    const float* Wn = Wh + (size_t)(2 * CH + j) * CH;

    for (int t = 0; t < CT; t++) {
        int cur = t & 1;
        const float* hsrc = g_hbuf + cur * CB * CH;
        for (int i = tid; i < CB * CH / 4; i += 256)
            ((float4*)h_s)[i] = ((const float4*)hsrc)[i];
        __syncthreads();

        float accr[CB], accz[CB], accn[CB];
        #pragma unroll
        for (int b = 0; b < CB; b++) { accr[b] = 0.f; accz[b] = 0.f; accn[b] = 0.f; }
        for (int k = lane * 4; k < CH; k += 128) {
            float4 wr = *(const float4*)(Wr + k);
            float4 wz = *(const float4*)(Wz + k);
            float4 wn = *(const float4*)(Wn + k);
            #pragma unroll
            for (int b = 0; b < CB; b++) {
                float4 hv = *(const float4*)(h_s + b * CH + k);
                accr[b] += wr.x * hv.x + wr.y * hv.y + wr.z * hv.z + wr.w * hv.w;
                accz[b] += wz.x * hv.x + wz.y * hv.y + wz.z * hv.z + wz.w * hv.w;
                accn[b] += wn.x * hv.x + wn.y * hv.y + wn.z * hv.z + wn.w * hv.w;
            }
        }
        #pragma unroll
        for (int b = 0; b < CB; b++) {
            #pragma unroll
            for (int o = 16; o; o >>= 1) {
                accr[b] += __shfl_xor_sync(0xffffffffu, accr[b], o);
                accz[b] += __shfl_xor_sync(0xffffffffu, accz[b], o);
                accn[b] += __shfl_xor_sync(0xffffffffu, accn[b], o);
            }
        }
        if (lane == 0) {
            #pragma unroll
            for (int b = 0; b < CB; b++) {
                const float* gib = gi + (size_t)(b * CT + t) * C3H;
                float ir = gib[0 * CH + j], iz = gib[1 * CH + j], inn = gib[2 * CH + j];
                float hprev = h_s[b * CH + j];
                float r = 1.f / (1.f + expf(-(ir + accr[b] + bhr)));
                float z = 1.f / (1.f + expf(-(iz + accz[b] + bhz)));
                float n = tanhf(inn + r * (accn[b] + bhn));
                float hn = (1.f - z) * n + z * hprev;
                g_hbuf[(cur ^ 1) * CB * CH + b * CH + j] = hn;
                hout[(size_t)(b * CT + t) * CH + j] = hn;
            }
        }
        grid_sync_all(gridDim.x);
    }
}

// ---------------- small attention scores (one warp per dot), N in {16,128} ----------------
__global__ void attn_scores_kernel(const float* __restrict__ q, const float* __restrict__ proj,
                                   float* __restrict__ out, int N) {
    int gw = (blockIdx.x * blockDim.x + threadIdx.x) >> 5;
    int lane = threadIdx.x & 31;
    if (gw >= CB * CT * N) return;
    int n = gw % N;
    int bt = gw / N;
    int b = bt / CT;
    const float* qp = q + (size_t)bt * CH;
    const float* pp = proj + (size_t)(b * N + n) * CH;
    float acc = 0.f;
    for (int k = lane * 4; k < CH; k += 128) {
        float4 qa = *(const float4*)(qp + k);
        float4 pa = *(const float4*)(pp + k);
        acc += qa.x * pa.x + qa.y * pa.y + qa.z * pa.z + qa.w * pa.w;
    }
    #pragma unroll
    for (int o = 16; o; o >>= 1) acc += __shfl_xor_sync(0xffffffffu, acc, o);
    if (lane == 0) out[gw] = acc;
}

// ---------------- fused masked softmaxes + hierarchical combine + final softmax ----------------
__global__ __launch_bounds__(256) void combine_kernel(
    const int* __restrict__ s_len, const int* __restrict__ u_len, const int* __restrict__ w_len,
    const int* __restrict__ seg, const int* __restrict__ utt)
{
    int bt = blockIdx.x, b = bt / CT, tid = threadIdx.x;
    __shared__ float ss[CS];
    __shared__ float su[CU];
    __shared__ float sw[CW];
    __shared__ float red[32];
    int sl = s_len[b], ul = u_len[b], wl = w_len[b];

    if (tid < 32) {
        float v = (tid < sl) ? g_sc_s[bt * CS + tid] : -INFINITY;
        float m = v;
        #pragma unroll
        for (int o = 16; o; o >>= 1) m = fmaxf(m, __shfl_xor_sync(0xffffffffu, m, o));
        float e = (tid < sl) ? expf(v - m) : 0.f;
        float s = e;
        #pragma unroll
        for (int o = 16; o; o >>= 1) s += __shfl_xor_sync(0xffffffffu, s, o);
        if (tid < CS) ss[tid] = e / s;
    }
    float uv = (tid < CU && tid < ul) ? g_sc_u[bt * CU + tid] : -INFINITY;
    float um = blockReduceMax256(uv, red);
    float ue = (tid < CU && tid < ul) ? expf(uv - um) : 0.f;
    float us = blockReduceSum256(ue, red);
    if (tid < CU) su[tid] = ue / us;
    float wv[4], we[4];
    float wm = -INFINITY;
    #pragma unroll
    for (int i = 0; i < 4; i++) {
        int idx = tid + 256 * i;
        wv[i] = (idx < wl) ? g_sc_w[(size_t)bt * CW + idx] : -INFINITY;
        wm = fmaxf(wm, wv[i]);
    }
    wm = blockReduceMax256(wm, red);
    float wsum = 0.f;
    #pragma unroll
    for (int i = 0; i < 4; i++) {
        int idx = tid + 256 * i;
        we[i] = (idx < wl) ? expf(wv[i] - wm) : 0.f;
        wsum += we[i];
    }
    wsum = blockReduceSum256(wsum, red);
    #pragma unroll
    for (int i = 0; i < 4; i++) sw[tid + 256 * i] = we[i] / wsum;
    __syncthreads();
    if (tid < CU) {
        float v2 = (tid < ul) ? ss[seg[b * CU + tid]] * su[tid] : 0.f;
        su[tid] = v2;
    }
    __syncthreads();
    float pv[4];
    #pragma unroll
    for (int i = 0; i < 4; i++) {
        int idx = tid + 256 * i;
        pv[i] = (idx < wl) ? su[utt[b * CW + idx]] * sw[idx] : 0.f;
    }
    float pm = fmaxf(fmaxf(pv[0], pv[1]), fmaxf(pv[2], pv[3]));
    pm = blockReduceMax256(pm, red);
    float pe[4];
    float psum = 0.f;
    #pragma unroll
    for (int i = 0; i < 4; i++) { pe[i] = expf(pv[i] - pm); psum += pe[i]; }
    psum = blockReduceSum256(psum, red);
    #pragma unroll
    for (int i = 0; i < 4; i++)
        g_suw[(size_t)bt * CW + tid + 256 * i] = pe[i] / psum;
}

// ---------------- per-batch transpose of w_output: [B,W,2M] -> [B,2M,W] ----------------
__global__ void transpose_w_kernel(const float* __restrict__ wo) {
    __shared__ float tile[32][33];
    int b = blockIdx.z;
    int w0 = blockIdx.x * 32, m0 = blockIdx.y * 32;
    int x = threadIdx.x, y = threadIdx.y;
    #pragma unroll
    for (int i = 0; i < 32; i += 8)
        tile[y + i][x] = wo[((size_t)b * CW + (w0 + y + i)) * CM2 + m0 + x];
    __syncthreads();
    #pragma unroll
    for (int i = 0; i < 32; i += 8)
        g_wT[((size_t)b * CM2 + (m0 + y + i)) * CW + w0 + x] = tile[x][y + i];
}

// ---------------- copy rnn_out into second half of feature matrix ----------------
__global__ void copy_rnn_kernel() {
    int i = blockIdx.x * blockDim.x + threadIdx.x;
    if (i < CB * CT * CH) {
        int bt = i / CH, j = i - bt * CH;
        g_feat[(size_t)bt * CF + CM2 + j] = g_rnn[i];
    }
}

// ---------------- in-place log_softmax over V per (b,t) row ----------------
__global__ __launch_bounds__(256) void logsoftmax_kernel(float* __restrict__ out) {
    __shared__ float red[32];
    int row = blockIdx.x, tid = threadIdx.x;
    float* p = out + (size_t)row * CV;
    float m = -INFINITY;
    for (int i = tid; i < CV; i += 256) m = fmaxf(m, p[i]);
    m = blockReduceMax256(m, red);
    float s = 0.f;
    for (int i = tid; i < CV; i += 256) s += expf(p[i] - m);
    s = blockReduceSum256(s, red);
    float lse = m + logf(s);
    for (int i = tid; i < CV; i += 256) p[i] -= lse;
}

// ---------------- launch ----------------
extern "C" void kernel_launch(void* const* d_in, const int* in_sizes, int n_in,
                              void* d_out, int out_size) {
    const int*   target   = (const int*)d_in[0];
    const float* embedding= (const float*)d_in[1];
    const float* W_ih0    = (const float*)d_in[2];
    const float* W_hh0    = (const float*)d_in[3];
    const float* b_ih0    = (const float*)d_in[4];
    const float* b_hh0    = (const float*)d_in[5];
    const float* W_ih1    = (const float*)d_in[6];
    const float* W_hh1    = (const float*)d_in[7];
    const float* b_ih1    = (const float*)d_in[8];
    const float* b_hh1    = (const float*)d_in[9];
    const float* att_s_w  = (const float*)d_in[10];
    const float* att_s_b  = (const float*)d_in[11];
    const float* att_u_w  = (const float*)d_in[12];
    const float* att_u_b  = (const float*)d_in[13];
    const float* att_w_w  = (const float*)d_in[14];
    const float* att_w_b  = (const float*)d_in[15];
    const float* out_w    = (const float*)d_in[16];
    const float* out_b    = (const float*)d_in[17];
    const float* s_output = (const float*)d_in[18];
    const float* u_output = (const float*)d_in[19];
    const float* w_output = (const float*)d_in[20];
    const int*   s_len    = (const int*)d_in[21];
    const int*   u_len    = (const int*)d_in[22];
    const int*   w_len    = (const int*)d_in[23];
    const int*   seg      = (const int*)d_in[24];
    const int*   utt      = (const int*)d_in[25];
    float* out = (float*)d_out;

    float *p_emb, *p_gi, *p_h1, *p_rnn, *p_ps, *p_pu, *p_pw, *p_scs, *p_scu, *p_scw, *p_suw, *p_wT, *p_feat;
    cudaGetSymbolAddress((void**)&p_emb, g_emb);
    cudaGetSymbolAddress((void**)&p_gi, g_gi);
    cudaGetSymbolAddress((void**)&p_h1, g_h1);
    cudaGetSymbolAddress((void**)&p_rnn, g_rnn);
    cudaGetSymbolAddress((void**)&p_ps, g_proj_s);
    cudaGetSymbolAddress((void**)&p_pu, g_proj_u);
    cudaGetSymbolAddress((void**)&p_pw, g_proj_w);
    cudaGetSymbolAddress((void**)&p_scs, g_sc_s);
    cudaGetSymbolAddress((void**)&p_scu, g_sc_u);
    cudaGetSymbolAddress((void**)&p_scw, g_sc_w);
    cudaGetSymbolAddress((void**)&p_suw, g_suw);
    cudaGetSymbolAddress((void**)&p_wT, g_wT);
    cudaGetSymbolAddress((void**)&p_feat, g_feat);

    // 1. embedding gather
    embed_kernel<<<(CB * CT * CE + 255) / 256, 256>>>(target, embedding);
    // 2. gi0 = emb @ W_ih0^T + b_ih0   [1024, 3072], K=512
    tgemm_nt<<<dim3((CB * CT) / 128, C3H / 128, 1), 256>>>(p_emb, W_ih0, b_ih0, p_gi,
        CB * CT, C3H, CE, C3H, 0, 0, 0);
    // 3. GRU layer 0 (persistent)
    gru_layer_kernel<<<128, 256>>>(p_gi, W_hh0, b_hh0, p_h1);
    // 4. gi1 = h1 @ W_ih1^T + b_ih1    [1024, 3072], K=1024
    tgemm_nt<<<dim3((CB * CT) / 128, C3H / 128, 1), 256>>>(p_h1, W_ih1, b_ih1, p_gi,
        CB * CT, C3H, CH, C3H, 0, 0, 0);
    // 5. GRU layer 1
    gru_layer_kernel<<<128, 256>>>(p_gi, W_hh1, b_hh1, p_rnn);
    // 6. attention memory projections
    tgemm_nt<<<dim3((CB * CS) / 128, CH / 128, 1), 256>>>(s_output, att_s_w, att_s_b, p_ps,
        CB * CS, CH, CM, CH, 0, 0, 0);
    tgemm_nt<<<dim3((CB * CU) / 128, CH / 128, 1), 256>>>(u_output, att_u_w, att_u_b, p_pu,
        CB * CU, CH, CM, CH, 0, 0, 0);
    tgemm_nt<<<dim3((CB * CW) / 128, CH / 128, 1), 256>>>(w_output, att_w_w, att_w_b, p_pw,
        CB * CW, CH, CM2, CH, 0, 0, 0);
    // 7. raw scores
    attn_scores_kernel<<<(CB * CT * CS) / 8, 256>>>(p_rnn, p_ps, p_scs, CS);
    attn_scores_kernel<<<(CB * CT * CU) / 8, 256>>>(p_rnn, p_pu, p_scu, CU);
    tgemm_nt<<<dim3(CT / 128, CW / 128, CB), 256>>>(p_rnn, p_pw, nullptr, p_scw,
        CT, CW, CH, CW, (long)CT * CH, (long)CW * CH, (long)CT * CW);
    // 8. masked softmaxes + hierarchical combine + final softmax
    combine_kernel<<<CB * CT, 256>>>(s_len, u_len, w_len, seg, utt);
    // 9. context = suw @ w_output  (needs w_output^T per batch for NT gemm)
    transpose_w_kernel<<<dim3(CW / 32, CM2 / 32, CB), dim3(32, 8)>>>(w_output);
    tgemm_nt<<<dim3(CT / 128, CM2 / 128, CB), 256>>>(p_suw, p_wT, nullptr, p_feat,
        CT, CM2, CW, CF, (long)CT * CW, (long)CM2 * CW, (long)CT * CF);
    // 10. feat[:, 1024:2048] = rnn_out
    copy_rnn_kernel<<<(CB * CT * CH + 255) / 256, 256>>>();
    // 11. logits = feat @ out_w^T + out_b  -> d_out   [1024, 32000], K=2048
    tgemm_nt<<<dim3((CB * CT) / 128, CV / 128, 1), 256>>>(p_feat, out_w, out_b, out,
        CB * CT, CV, CF, CV, 0, 0, 0);
    // 12. in-place log_softmax
    logsoftmax_kernel<<<CB * CT, 256>>>(out);
}

// round 6
// speedup vs baseline: 1.8938x; 1.0035x over previous
#include <cuda_runtime.h>
#include <cuda_bf16.h>
#include <math.h>

// ---------------- problem constants ----------------
#define CB 8       // batch
#define CT 128     // time
#define CE 512     // embed dim
#define CH 1024    // hidden
#define CM 512     // mem hidden
#define CM2 1024   // 2*M
#define CS 16
#define CU 128
#define CW 1024
#define CV 32000
#define C3H 3072
#define CF 2048    // H + 2M (feature dim into output proj)

// ---------------- scratch (device globals; no runtime alloc) ----------------
__device__ float g_emb[CB * CT * CE];
__device__ float g_gi[CB * CT * C3H];
__device__ float g_h1[CB * CT * CH];
__device__ float g_rnn[CB * CT * CH];
__device__ float g_hbuf[2 * CB * CH];
__device__ float g_proj_s[CB * CS * CH];
__device__ float g_proj_u[CB * CU * CH];
__device__ float g_proj_w[CB * CW * CH];
__device__ float g_sc_s[CB * CT * CS];
__device__ float g_sc_u[CB * CT * CU];
__device__ float g_sc_w[CB * CT * CW];
__device__ float g_suw[CB * CT * CW];
__device__ float g_wT[CB * CM2 * CW];
__device__ float g_feat[CB * CT * CF];
__device__ unsigned g_bar_arr = 0;
__device__ unsigned g_bar_gen = 0;

// ---------------- grid barrier (persistent GRU kernel) ----------------
__device__ __forceinline__ void grid_sync_all(unsigned nb) {
    __threadfence();
    __syncthreads();
    if (threadIdx.x == 0) {
        unsigned gen = atomicAdd(&g_bar_gen, 0u);
        if (atomicAdd(&g_bar_arr, 1u) == nb - 1u) {
            atomicExch(&g_bar_arr, 0u);
            __threadfence();
            atomicAdd(&g_bar_gen, 1u);
        } else {
            while (atomicAdd(&g_bar_gen, 0u) == gen) { __nanosleep(64); }
        }
    }
    __syncthreads();
}

// ---------------- block reductions (256 threads fixed) ----------------
__device__ __forceinline__ float blockReduceMax256(float v, float* red) {
    #pragma unroll
    for (int o = 16; o; o >>= 1) v = fmaxf(v, __shfl_xor_sync(0xffffffffu, v, o));
    if ((threadIdx.x & 31) == 0) red[threadIdx.x >> 5] = v;
    __syncthreads();
    if (threadIdx.x < 32) {
        float r = (threadIdx.x < 8) ? red[threadIdx.x] : -INFINITY;
        #pragma unroll
        for (int o = 4; o; o >>= 1) r = fmaxf(r, __shfl_xor_sync(0xffffffffu, r, o));
        if (threadIdx.x == 0) red[0] = r;
    }
    __syncthreads();
    float out = red[0];
    __syncthreads();
    return out;
}

__device__ __forceinline__ float blockReduceSum256(float v, float* red) {
    #pragma unroll
    for (int o = 16; o; o >>= 1) v += __shfl_xor_sync(0xffffffffu, v, o);
    if ((threadIdx.x & 31) == 0) red[threadIdx.x >> 5] = v;
    __syncthreads();
    if (threadIdx.x < 32) {
        float r = (threadIdx.x < 8) ? red[threadIdx.x] : 0.f;
        #pragma unroll
        for (int o = 4; o; o >>= 1) r += __shfl_xor_sync(0xffffffffu, r, o);
        if (threadIdx.x == 0) red[0] = r;
    }
    __syncthreads();
    float out = red[0];
    __syncthreads();
    return out;
}

// ---------------- embedding gather ----------------
__global__ void embed_kernel(const int* __restrict__ target, const float* __restrict__ emb) {
    int i = blockIdx.x * blockDim.x + threadIdx.x;
    if (i < CB * CT * CE) {
        int bt = i / CE, e = i - bt * CE;
        g_emb[i] = emb[(size_t)target[bt] * CE + e];
    }
}

// ---------------- tf32 helpers ----------------
__device__ __forceinline__ unsigned f2tf(float x) {
    unsigned r;
    asm("cvt.rna.tf32.f32 %0, %1;" : "=r"(r) : "f"(x));
    return r;
}

__device__ __forceinline__ void mma_tf32(float* d, const unsigned* a, const unsigned* b) {
    asm volatile(
        "mma.sync.aligned.m16n8k8.row.col.f32.tf32.tf32.f32 "
        "{%0,%1,%2,%3}, {%4,%5,%6,%7}, {%8,%9}, {%0,%1,%2,%3};"
        : "+f"(d[0]), "+f"(d[1]), "+f"(d[2]), "+f"(d[3])
        : "r"(a[0]), "r"(a[1]), "r"(a[2]), "r"(a[3]), "r"(b[0]), "r"(b[1]));
}

// ---------------- tf32 tensor-core NT GEMM ----------------
// C[m,n] = A[m,:] . B[n,:] + bias[n].  A:[M,K] row-major, B:[N,K] row-major.
// Requires M%128==0, N%128==0, K%32==0 (all call sites satisfy).
// Grid: (M/128, N/128, batch). Block tile 128x128, K-tile 32. 8 warps: 2(M) x 4(N),
// warp tile 64x32 via m16n8k8. Smem: k-major groups of 4 with XOR swizzle:
//   word index = kq*512 + (((row<<2)|j) ^ (kq<<2)),  row in [0,128), kq=k/4, j=k%4
// -> fragment LDS conflict-free; staging STS 4-way (acceptable, MMA-bound).
__global__ __launch_bounds__(256, 2) void tgemm_nt(
    const float* __restrict__ A, const float* __restrict__ Bm,
    const float* __restrict__ bias, float* __restrict__ C,
    int M, int N, int K, int ldc,
    long sA, long sB, long sC)
{
    __shared__ unsigned As[8 * 512];   // 16 KB
    __shared__ unsigned Bs[8 * 512];   // 16 KB
    const float* Ab = A + (size_t)blockIdx.z * sA;
    const float* Bb = Bm + (size_t)blockIdx.z * sB;
    float* Cb = C + (size_t)blockIdx.z * sC;
    int m0 = blockIdx.x * 128, n0 = blockIdx.y * 128;
    int tid = threadIdx.x;
    int warp = tid >> 5, lane = tid & 31;
    int wm = (warp >> 2) * 64;       // warp M offset (0 or 64)
    int wn = (warp & 3) * 32;        // warp N offset
    int lr = lane >> 2, lq = lane & 3;

    float acc[4][4][4];
    #pragma unroll
    for (int mi = 0; mi < 4; mi++)
        #pragma unroll
        for (int ni = 0; ni < 4; ni++)
            #pragma unroll
            for (int r = 0; r < 4; r++) acc[mi][ni][r] = 0.f;

    for (int kt = 0; kt < K; kt += 32) {
        // ---- stage A,B tiles (fp32 -> tf32) ----
        #pragma unroll
        for (int i = 0; i < 4; i++) {
            int idx = tid + 256 * i;
            int row = idx >> 3, kq = idx & 7;
            float4 av = *(const float4*)(Ab + (size_t)(m0 + row) * K + kt + kq * 4);
            float4 bv = *(const float4*)(Bb + (size_t)(n0 + row) * K + kt + kq * 4);
            unsigned base = kq * 512 + ((row << 2) ^ (kq << 2));
            As[base + 0] = f2tf(av.x); As[base + 1] = f2tf(av.y);
            As[base + 2] = f2tf(av.z); As[base + 3] = f2tf(av.w);
            Bs[base + 0] = f2tf(bv.x); Bs[base + 1] = f2tf(bv.y);
            Bs[base + 2] = f2tf(bv.z); Bs[base + 3] = f2tf(bv.w);
        }
        __syncthreads();

        // ---- compute: 4 k-steps of 8 ----
        #pragma unroll
        for (int kk = 0; kk < 4; kk++) {
            int kq0 = 2 * kk, kq1 = 2 * kk + 1;
            unsigned a[4][4], b[4][2];
            #pragma unroll
            for (int mi = 0; mi < 4; mi++) {
                int m = wm + mi * 16 + lr;
                a[mi][0] = As[kq0 * 512 + (((m << 2) | lq) ^ (kq0 << 2))];
                a[mi][1] = As[kq0 * 512 + ((((m + 8) << 2) | lq) ^ (kq0 << 2))];
                a[mi][2] = As[kq1 * 512 + (((m << 2) | lq) ^ (kq1 << 2))];
                a[mi][3] = As[kq1 * 512 + ((((m + 8) << 2) | lq) ^ (kq1 << 2))];
            }
            #pragma unroll
            for (int ni = 0; ni < 4; ni++) {
                int n = wn + ni * 8 + lr;
                b[ni][0] = Bs[kq0 * 512 + (((n << 2) | lq) ^ (kq0 << 2))];
                b[ni][1] = Bs[kq1 * 512 + (((n << 2) | lq) ^ (kq1 << 2))];
            }
            #pragma unroll
            for (int mi = 0; mi < 4; mi++)
                #pragma unroll
                for (int ni = 0; ni < 4; ni++)
                    mma_tf32(acc[mi][ni], a[mi], b[ni]);
        }
        __syncthreads();
    }

    // ---- epilogue ----
    #pragma unroll
    for (int mi = 0; mi < 4; mi++) {
        #pragma unroll
        for (int ni = 0; ni < 4; ni++) {
            int m = m0 + wm + mi * 16 + lr;
            int n = n0 + wn + ni * 8 + lq * 2;
            float b0 = bias ? bias[n] : 0.f;
            float b1 = bias ? bias[n + 1] : 0.f;
            float2 v0 = make_float2(acc[mi][ni][0] + b0, acc[mi][ni][1] + b1);
            float2 v1 = make_float2(acc[mi][ni][2] + b0, acc[mi][ni][3] + b1);
            *(float2*)(Cb + (size_t)m * ldc + n) = v0;
            *(float2*)(Cb + (size_t)(m + 8) * ldc + n) = v1;
        }
    }
}

// ---------------- persistent GRU layer ----------------
__global__ __launch_bounds__(256) void gru_layer_kernel(
    const float* __restrict__ gi, const float* __restrict__ Wh,
    const float* __restrict__ bh, float* __restrict__ hout)
{
    __shared__ float h_s[CB * CH];   // 32 KB
    int tid = threadIdx.x;
    for (int i = tid + blockIdx.x * 256; i < 2 * CB * CH; i += gridDim.x * 256)
        g_hbuf[i] = 0.f;
    grid_sync_all(gridDim.x);

    int warp = tid >> 5, lane = tid & 31;
    int j = blockIdx.x * 8 + warp;
    float bhr = bh[0 * CH + j], bhz = bh[1 * CH + j], bhn = bh[2 * CH + j];
    const float* Wr = Wh + (size_t)(0 * CH + j) * CH;
    const float* Wz = Wh + (size_t)(1 * CH + j) * CH;
    const float* Wn = Wh + (size_t)(2 * CH + j) * CH;

    for (int t = 0; t < CT; t++) {
        int cur = t & 1;
        const float* hsrc = g_hbuf + cur * CB * CH;
        for (int i = tid; i < CB * CH / 4; i += 256)
            ((float4*)h_s)[i] = ((const float4*)hsrc)[i];
        __syncthreads();

        float accr[CB], accz[CB], accn[CB];
        #pragma unroll
        for (int b = 0; b < CB; b++) { accr[b] = 0.f; accz[b] = 0.f; accn[b] = 0.f; }
        for (int k = lane * 4; k < CH; k += 128) {
            float4 wr = *(const float4*)(Wr + k);
            float4 wz = *(const float4*)(Wz + k);
            float4 wn = *(const float4*)(Wn + k);
            #pragma unroll
            for (int b = 0; b < CB; b++) {
                float4 hv = *(const float4*)(h_s + b * CH + k);
                accr[b] += wr.x * hv.x + wr.y * hv.y + wr.z * hv.z + wr.w * hv.w;
                accz[b] += wz.x * hv.x + wz.y * hv.y + wz.z * hv.z + wz.w * hv.w;
                accn[b] += wn.x * hv.x + wn.y * hv.y + wn.z * hv.z + wn.w * hv.w;
            }
        }
        #pragma unroll
        for (int b = 0; b < CB; b++) {
            #pragma unroll
            for (int o = 16; o; o >>= 1) {
                accr[b] += __shfl_xor_sync(0xffffffffu, accr[b], o);
                accz[b] += __shfl_xor_sync(0xffffffffu, accz[b], o);
                accn[b] += __shfl_xor_sync(0xffffffffu, accn[b], o);
            }
        }
        if (lane == 0) {
            #pragma unroll
            for (int b = 0; b < CB; b++) {
                const float* gib = gi + (size_t)(b * CT + t) * C3H;
                float ir = gib[0 * CH + j], iz = gib[1 * CH + j], inn = gib[2 * CH + j];
                float hprev = h_s[b * CH + j];
                float r = 1.f / (1.f + expf(-(ir + accr[b] + bhr)));
                float z = 1.f / (1.f + expf(-(iz + accz[b] + bhz)));
                float n = tanhf(inn + r * (accn[b] + bhn));
                float hn = (1.f - z) * n + z * hprev;
                g_hbuf[(cur ^ 1) * CB * CH + b * CH + j] = hn;
                hout[(size_t)(b * CT + t) * CH + j] = hn;
            }
        }
        grid_sync_all(gridDim.x);
    }
}

// ---------------- small attention scores (one warp per dot), N in {16,128} ----------------
__global__ void attn_scores_kernel(const float* __restrict__ q, const float* __restrict__ proj,
                                   float* __restrict__ out, int N) {
    int gw = (blockIdx.x * blockDim.x + threadIdx.x) >> 5;
    int lane = threadIdx.x & 31;
    if (gw >= CB * CT * N) return;
    int n = gw % N;
    int bt = gw / N;
    int b = bt / CT;
    const float* qp = q + (size_t)bt * CH;
    const float* pp = proj + (size_t)(b * N + n) * CH;
    float acc = 0.f;
    for (int k = lane * 4; k < CH; k += 128) {
        float4 qa = *(const float4*)(qp + k);
        float4 pa = *(const float4*)(pp + k);
        acc += qa.x * pa.x + qa.y * pa.y + qa.z * pa.z + qa.w * pa.w;
    }
    #pragma unroll
    for (int o = 16; o; o >>= 1) acc += __shfl_xor_sync(0xffffffffu, acc, o);
    if (lane == 0) out[gw] = acc;
}

// ---------------- fused masked softmaxes + hierarchical combine + final softmax ----------------
__global__ __launch_bounds__(256) void combine_kernel(
    const int* __restrict__ s_len, const int* __restrict__ u_len, const int* __restrict__ w_len,
    const int* __restrict__ seg, const int* __restrict__ utt)
{
    int bt = blockIdx.x, b = bt / CT, tid = threadIdx.x;
    __shared__ float ss[CS];
    __shared__ float su[CU];
    __shared__ float sw[CW];
    __shared__ float red[32];
    int sl = s_len[b], ul = u_len[b], wl = w_len[b];

    if (tid < 32) {
        float v = (tid < sl) ? g_sc_s[bt * CS + tid] : -INFINITY;
        float m = v;
        #pragma unroll
        for (int o = 16; o; o >>= 1) m = fmaxf(m, __shfl_xor_sync(0xffffffffu, m, o));
        float e = (tid < sl) ? expf(v - m) : 0.f;
        float s = e;
        #pragma unroll
        for (int o = 16; o; o >>= 1) s += __shfl_xor_sync(0xffffffffu, s, o);
        if (tid < CS) ss[tid] = e / s;
    }
    float uv = (tid < CU && tid < ul) ? g_sc_u[bt * CU + tid] : -INFINITY;
    float um = blockReduceMax256(uv, red);
    float ue = (tid < CU && tid < ul) ? expf(uv - um) : 0.f;
    float us = blockReduceSum256(ue, red);
    if (tid < CU) su[tid] = ue / us;
    float wv[4], we[4];
    float wm = -INFINITY;
    #pragma unroll
    for (int i = 0; i < 4; i++) {
        int idx = tid + 256 * i;
        wv[i] = (idx < wl) ? g_sc_w[(size_t)bt * CW + idx] : -INFINITY;
        wm = fmaxf(wm, wv[i]);
    }
    wm = blockReduceMax256(wm, red);
    float wsum = 0.f;
    #pragma unroll
    for (int i = 0; i < 4; i++) {
        int idx = tid + 256 * i;
        we[i] = (idx < wl) ? expf(wv[i] - wm) : 0.f;
        wsum += we[i];
    }
    wsum = blockReduceSum256(wsum, red);
    #pragma unroll
    for (int i = 0; i < 4; i++) sw[tid + 256 * i] = we[i] / wsum;
    __syncthreads();
    if (tid < CU) {
        float v2 = (tid < ul) ? ss[seg[b * CU + tid]] * su[tid] : 0.f;
        su[tid] = v2;
    }
    __syncthreads();
    float pv[4];
    #pragma unroll
    for (int i = 0; i < 4; i++) {
        int idx = tid + 256 * i;
        pv[i] = (idx < wl) ? su[utt[b * CW + idx]] * sw[idx] : 0.f;
    }
    float pm = fmaxf(fmaxf(pv[0], pv[1]), fmaxf(pv[2], pv[3]));
    pm = blockReduceMax256(pm, red);
    float pe[4];
    float psum = 0.f;
    #pragma unroll
    for (int i = 0; i < 4; i++) { pe[i] = expf(pv[i] - pm); psum += pe[i]; }
    psum = blockReduceSum256(psum, red);
    #pragma unroll
    for (int i = 0; i < 4; i++)
        g_suw[(size_t)bt * CW + tid + 256 * i] = pe[i] / psum;
}

// ---------------- per-batch transpose of w_output: [B,W,2M] -> [B,2M,W] ----------------
__global__ void transpose_w_kernel(const float* __restrict__ wo) {
    __shared__ float tile[32][33];
    int b = blockIdx.z;
    int w0 = blockIdx.x * 32, m0 = blockIdx.y * 32;
    int x = threadIdx.x, y = threadIdx.y;
    #pragma unroll
    for (int i = 0; i < 32; i += 8)
        tile[y + i][x] = wo[((size_t)b * CW + (w0 + y + i)) * CM2 + m0 + x];
    __syncthreads();
    #pragma unroll
    for (int i = 0; i < 32; i += 8)
        g_wT[((size_t)b * CM2 + (m0 + y + i)) * CW + w0 + x] = tile[x][y + i];
}

// ---------------- copy rnn_out into second half of feature matrix ----------------
__global__ void copy_rnn_kernel() {
    int i = blockIdx.x * blockDim.x + threadIdx.x;
    if (i < CB * CT * CH) {
        int bt = i / CH, j = i - bt * CH;
        g_feat[(size_t)bt * CF + CM2 + j] = g_rnn[i];
    }
}

// ---------------- in-place log_softmax over V per (b,t) row ----------------
__global__ __launch_bounds__(256) void logsoftmax_kernel(float* __restrict__ out) {
    __shared__ float red[32];
    int row = blockIdx.x, tid = threadIdx.x;
    float* p = out + (size_t)row * CV;
    float m = -INFINITY;
    for (int i = tid; i < CV; i += 256) m = fmaxf(m, p[i]);
    m = blockReduceMax256(m, red);
    float s = 0.f;
    for (int i = tid; i < CV; i += 256) s += expf(p[i] - m);
    s = blockReduceSum256(s, red);
    float lse = m + logf(s);
    for (int i = tid; i < CV; i += 256) p[i] -= lse;
}

// ---------------- launch ----------------
extern "C" void kernel_launch(void* const* d_in, const int* in_sizes, int n_in,
                              void* d_out, int out_size) {
    const int*   target   = (const int*)d_in[0];
    const float* embedding= (const float*)d_in[1];
    const float* W_ih0    = (const float*)d_in[2];
    const float* W_hh0    = (const float*)d_in[3];
    const float* b_ih0    = (const float*)d_in[4];
    const float* b_hh0    = (const float*)d_in[5];
    const float* W_ih1    = (const float*)d_in[6];
    const float* W_hh1    = (const float*)d_in[7];
    const float* b_ih1    = (const float*)d_in[8];
    const float* b_hh1    = (const float*)d_in[9];
    const float* att_s_w  = (const float*)d_in[10];
    const float* att_s_b  = (const float*)d_in[11];
    const float* att_u_w  = (const float*)d_in[12];
    const float* att_u_b  = (const float*)d_in[13];
    const float* att_w_w  = (const float*)d_in[14];
    const float* att_w_b  = (const float*)d_in[15];
    const float* out_w    = (const float*)d_in[16];
    const float* out_b    = (const float*)d_in[17];
    const float* s_output = (const float*)d_in[18];
    const float* u_output = (const float*)d_in[19];
    const float* w_output = (const float*)d_in[20];
    const int*   s_len    = (const int*)d_in[21];
    const int*   u_len    = (const int*)d_in[22];
    const int*   w_len    = (const int*)d_in[23];
    const int*   seg      = (const int*)d_in[24];
    const int*   utt      = (const int*)d_in[25];
    float* out = (float*)d_out;

    float *p_emb, *p_gi, *p_h1, *p_rnn, *p_ps, *p_pu, *p_pw, *p_scs, *p_scu, *p_scw, *p_suw, *p_wT, *p_feat;
    cudaGetSymbolAddress((void**)&p_emb, g_emb);
    cudaGetSymbolAddress((void**)&p_gi, g_gi);
    cudaGetSymbolAddress((void**)&p_h1, g_h1);
    cudaGetSymbolAddress((void**)&p_rnn, g_rnn);
    cudaGetSymbolAddress((void**)&p_ps, g_proj_s);
    cudaGetSymbolAddress((void**)&p_pu, g_proj_u);
    cudaGetSymbolAddress((void**)&p_pw, g_proj_w);
    cudaGetSymbolAddress((void**)&p_scs, g_sc_s);
    cudaGetSymbolAddress((void**)&p_scu, g_sc_u);
    cudaGetSymbolAddress((void**)&p_scw, g_sc_w);
    cudaGetSymbolAddress((void**)&p_suw, g_suw);
    cudaGetSymbolAddress((void**)&p_wT, g_wT);
    cudaGetSymbolAddress((void**)&p_feat, g_feat);

    // 1. embedding gather
    embed_kernel<<<(CB * CT * CE + 255) / 256, 256>>>(target, embedding);
    // 2. gi0 = emb @ W_ih0^T + b_ih0   [1024, 3072], K=512
    tgemm_nt<<<dim3((CB * CT) / 128, C3H / 128, 1), 256>>>(p_emb, W_ih0, b_ih0, p_gi,
        CB * CT, C3H, CE, C3H, 0, 0, 0);
    // 3. GRU layer 0 (persistent)
    gru_layer_kernel<<<128, 256>>>(p_gi, W_hh0, b_hh0, p_h1);
    // 4. gi1 = h1 @ W_ih1^T + b_ih1    [1024, 3072], K=1024
    tgemm_nt<<<dim3((CB * CT) / 128, C3H / 128, 1), 256>>>(p_h1, W_ih1, b_ih1, p_gi,
        CB * CT, C3H, CH, C3H, 0, 0, 0);
    // 5. GRU layer 1
    gru_layer_kernel<<<128, 256>>>(p_gi, W_hh1, b_hh1, p_rnn);
    // 6. attention memory projections
    tgemm_nt<<<dim3((CB * CS) / 128, CH / 128, 1), 256>>>(s_output, att_s_w, att_s_b, p_ps,
        CB * CS, CH, CM, CH, 0, 0, 0);
    tgemm_nt<<<dim3((CB * CU) / 128, CH / 128, 1), 256>>>(u_output, att_u_w, att_u_b, p_pu,
        CB * CU, CH, CM, CH, 0, 0, 0);
    tgemm_nt<<<dim3((CB * CW) / 128, CH / 128, 1), 256>>>(w_output, att_w_w, att_w_b, p_pw,
        CB * CW, CH, CM2, CH, 0, 0, 0);
    // 7. raw scores
    attn_scores_kernel<<<(CB * CT * CS) / 8, 256>>>(p_rnn, p_ps, p_scs, CS);
    attn_scores_kernel<<<(CB * CT * CU) / 8, 256>>>(p_rnn, p_pu, p_scu, CU);
    tgemm_nt<<<dim3(CT / 128, CW / 128, CB), 256>>>(p_rnn, p_pw, nullptr, p_scw,
        CT, CW, CH, CW, (long)CT * CH, (long)CW * CH, (long)CT * CW);
    // 8. masked softmaxes + hierarchical combine + final softmax
    combine_kernel<<<CB * CT, 256>>>(s_len, u_len, w_len, seg, utt);
    // 9. context = suw @ w_output  (needs w_output^T per batch for NT gemm)
    transpose_w_kernel<<<dim3(CW / 32, CM2 / 32, CB), dim3(32, 8)>>>(w_output);
    tgemm_nt<<<dim3(CT / 128, CM2 / 128, CB), 256>>>(p_suw, p_wT, nullptr, p_feat,
        CT, CM2, CW, CF, (long)CT * CW, (long)CM2 * CW, (long)CT * CF);
    // 10. feat[:, 1024:2048] = rnn_out
    copy_rnn_kernel<<<(CB * CT * CH + 255) / 256, 256>>>();
    // 11. logits = feat @ out_w^T + out_b  -> d_out   [1024, 32000], K=2048
    tgemm_nt<<<dim3((CB * CT) / 128, CV / 128, 1), 256>>>(p_feat, out_w, out_b, out,
        CB * CT, CV, CF, CV, 0, 0, 0);
    // 12. in-place log_softmax
    logsoftmax_kernel<<<CB * CT, 256>>>(out);
}

// round 7
// speedup vs baseline: 2.2142x; 1.1692x over previous
#include <cuda_runtime.h>
#include <cuda_bf16.h>
#include <math.h>

// ---------------- problem constants ----------------
#define CB 8       // batch
#define CT 128     // time
#define CE 512     // embed dim
#define CH 1024    // hidden
#define CM 512     // mem hidden
#define CM2 1024   // 2*M
#define CS 16
#define CU 128
#define CW 1024
#define CV 32000
#define C3H 3072
#define CF 2048    // H + 2M

// ---------------- fp32 scratch ----------------
__device__ float g_gi[CB * CT * C3H];
__device__ float g_h1[CB * CT * CH];
__device__ float g_rnn[CB * CT * CH];
__device__ float g_hbuf[2 * CB * CH];
__device__ float g_proj_s[CB * CS * CH];
__device__ float g_proj_u[CB * CU * CH];
__device__ float g_sc_s[CB * CT * CS];
__device__ float g_sc_u[CB * CT * CU];
__device__ float g_sc_w[CB * CT * CW];
__device__ unsigned g_bar_arr = 0;
__device__ unsigned g_bar_gen = 0;

// ---------------- bf16 scratch (GEMM operands) ----------------
__device__ __nv_bfloat16 gb_emb[CB * CT * CE];
__device__ __nv_bfloat16 gb_h1[CB * CT * CH];
__device__ __nv_bfloat16 gb_rnn[CB * CT * CH];
__device__ __nv_bfloat16 gb_feat[CB * CT * CF];
__device__ __nv_bfloat16 gb_suw[CB * CT * CW];
__device__ __nv_bfloat16 gb_sout[CB * CS * CM];
__device__ __nv_bfloat16 gb_uout[CB * CU * CM];
__device__ __nv_bfloat16 gb_wout[CB * CW * CM2];
__device__ __nv_bfloat16 gb_wT[CB * CM2 * CW];
__device__ __nv_bfloat16 gb_pw[CB * CW * CH];
__device__ __nv_bfloat16 gb_Wih0[C3H * CE];
__device__ __nv_bfloat16 gb_Wih1[C3H * CH];
__device__ __nv_bfloat16 gb_atts[CH * CM];
__device__ __nv_bfloat16 gb_attu[CH * CM];
__device__ __nv_bfloat16 gb_attw[CH * CM2];
__device__ __nv_bfloat16 gb_outw[(size_t)CV * CF];   // 131 MB

// ---------------- grid barrier (persistent GRU kernel) ----------------
__device__ __forceinline__ void grid_sync_all(unsigned nb) {
    __threadfence();
    __syncthreads();
    if (threadIdx.x == 0) {
        unsigned gen = atomicAdd(&g_bar_gen, 0u);
        if (atomicAdd(&g_bar_arr, 1u) == nb - 1u) {
            atomicExch(&g_bar_arr, 0u);
            __threadfence();
            atomicAdd(&g_bar_gen, 1u);
        } else {
            while (atomicAdd(&g_bar_gen, 0u) == gen) { __nanosleep(64); }
        }
    }
    __syncthreads();
}

// ---------------- block reductions (256 threads fixed) ----------------
__device__ __forceinline__ float blockReduceMax256(float v, float* red) {
    #pragma unroll
    for (int o = 16; o; o >>= 1) v = fmaxf(v, __shfl_xor_sync(0xffffffffu, v, o));
    if ((threadIdx.x & 31) == 0) red[threadIdx.x >> 5] = v;
    __syncthreads();
    if (threadIdx.x < 32) {
        float r = (threadIdx.x < 8) ? red[threadIdx.x] : -INFINITY;
        #pragma unroll
        for (int o = 4; o; o >>= 1) r = fmaxf(r, __shfl_xor_sync(0xffffffffu, r, o));
        if (threadIdx.x == 0) red[0] = r;
    }
    __syncthreads();
    float out = red[0];
    __syncthreads();
    return out;
}

__device__ __forceinline__ float blockReduceSum256(float v, float* red) {
    #pragma unroll
    for (int o = 16; o; o >>= 1) v += __shfl_xor_sync(0xffffffffu, v, o);
    if ((threadIdx.x & 31) == 0) red[threadIdx.x >> 5] = v;
    __syncthreads();
    if (threadIdx.x < 32) {
        float r = (threadIdx.x < 8) ? red[threadIdx.x] : 0.f;
        #pragma unroll
        for (int o = 4; o; o >>= 1) r += __shfl_xor_sync(0xffffffffu, r, o);
        if (threadIdx.x == 0) red[0] = r;
    }
    __syncthreads();
    float out = red[0];
    __syncthreads();
    return out;
}

// ---------------- fp32 -> bf16 convert ----------------
__global__ void f2b_kernel(const float* __restrict__ src, __nv_bfloat16* __restrict__ dst, int n) {
    int i = (blockIdx.x * blockDim.x + threadIdx.x) * 4;
    if (i < n) {
        float4 v = *(const float4*)(src + i);
        __nv_bfloat162* d = (__nv_bfloat162*)(dst + i);
        d[0] = __floats2bfloat162_rn(v.x, v.y);
        d[1] = __floats2bfloat162_rn(v.z, v.w);
    }
}

// ---------------- embedding gather (writes bf16 directly) ----------------
__global__ void embed_kernel(const int* __restrict__ target, const float* __restrict__ emb) {
    int i = blockIdx.x * blockDim.x + threadIdx.x;
    if (i < CB * CT * CE) {
        int bt = i / CE, e = i - bt * CE;
        gb_emb[i] = __float2bfloat16(emb[(size_t)target[bt] * CE + e]);
    }
}

// ---------------- bf16 mma helper ----------------
__device__ __forceinline__ void mma_bf16(float* d, const unsigned* a, const unsigned* b) {
    asm volatile(
        "mma.sync.aligned.m16n8k16.row.col.f32.bf16.bf16.f32 "
        "{%0,%1,%2,%3}, {%4,%5,%6,%7}, {%8,%9}, {%0,%1,%2,%3};"
        : "+f"(d[0]), "+f"(d[1]), "+f"(d[2]), "+f"(d[3])
        : "r"(a[0]), "r"(a[1]), "r"(a[2]), "r"(a[3]), "r"(b[0]), "r"(b[1]));
}

__device__ __forceinline__ void cpa16(unsigned dst, const void* src) {
    asm volatile("cp.async.ca.shared.global [%0], [%1], 16;" :: "r"(dst), "l"(src));
}

// ---------------- bf16 tensor-core NT GEMM, 2-stage cp.async pipeline ----------------
// C[m,n] = A[m,:].B[n,:] + bias[n].  A:[M,K] bf16 row-major, B:[N,K] bf16 row-major.
// Block tile 128x128, KT=32. 8 warps (2M x 4N), warp tile 64x32, m16n8k16.
// Smem: per row 16 u32 words (32 bf16). 16B-granule swizzle: g' = g ^ ((row>>1)&3)
// -> conflict-free for cp.async stores and all fragment LDS reads.
// Requires M%128==0, N%128==0, K%32==0.
template<bool OB>
__global__ __launch_bounds__(256) void bgemm_nt(
    const __nv_bfloat16* __restrict__ A, const __nv_bfloat16* __restrict__ Bm,
    const float* __restrict__ bias, void* __restrict__ Cv,
    int M, int N, int K, int ldc, long sA, long sB, long sC)
{
    __shared__ unsigned As[2][2048];   // 16 KB
    __shared__ unsigned Bs[2][2048];   // 16 KB
    const __nv_bfloat16* Ab = A + (size_t)blockIdx.z * sA + (size_t)(blockIdx.x * 128) * K;
    const __nv_bfloat16* Bb = Bm + (size_t)blockIdx.z * sB + (size_t)(blockIdx.y * 128) * K;
    int tid = threadIdx.x;
    int warp = tid >> 5, lane = tid & 31;
    int wm = (warp >> 2) * 64, wn = (warp & 3) * 32;
    int lr = lane >> 2, lq = lane & 3;

    // staging: thread -> granules (r0, g0) and (r0+64, g0); swizzle identical for +64
    int r0 = tid >> 2, g0 = tid & 3;
    unsigned woff0 = (unsigned)((r0 * 16 + (g0 ^ ((r0 >> 1) & 3)) * 4) * 4);  // byte offset
    unsigned baseA0 = (unsigned)__cvta_generic_to_shared(&As[0][0]);
    unsigned baseA1 = (unsigned)__cvta_generic_to_shared(&As[1][0]);
    unsigned baseB0 = (unsigned)__cvta_generic_to_shared(&Bs[0][0]);
    unsigned baseB1 = (unsigned)__cvta_generic_to_shared(&Bs[1][0]);
    const __nv_bfloat16* srcA0 = Ab + (size_t)r0 * K + g0 * 8;
    const __nv_bfloat16* srcB0 = Bb + (size_t)r0 * K + g0 * 8;

    float acc[4][4][4];
    #pragma unroll
    for (int mi = 0; mi < 4; mi++)
        #pragma unroll
        for (int ni = 0; ni < 4; ni++)
            #pragma unroll
            for (int r = 0; r < 4; r++) acc[mi][ni][r] = 0.f;

    int nt = K / 32;
    // prologue: stage 0
    {
        cpa16(baseA0 + woff0, srcA0);
        cpa16(baseA0 + woff0 + 4096, srcA0 + (size_t)64 * K);
        cpa16(baseB0 + woff0, srcB0);
        cpa16(baseB0 + woff0 + 4096, srcB0 + (size_t)64 * K);
        asm volatile("cp.async.commit_group;");
    }

    for (int it = 0; it < nt; it++) {
        int s = it & 1;
        if (it + 1 < nt) {
            int kt = (it + 1) * 32;
            unsigned ba = (s == 0) ? baseA1 : baseA0;
            unsigned bb = (s == 0) ? baseB1 : baseB0;
            cpa16(ba + woff0, srcA0 + kt);
            cpa16(ba + woff0 + 4096, srcA0 + (size_t)64 * K + kt);
            cpa16(bb + woff0, srcB0 + kt);
            cpa16(bb + woff0 + 4096, srcB0 + (size_t)64 * K + kt);
            asm volatile("cp.async.commit_group;");
            asm volatile("cp.async.wait_group 1;");
        } else {
            asm volatile("cp.async.wait_group 0;");
        }
        __syncthreads();

        #pragma unroll
        for (int ks = 0; ks < 2; ks++) {
            int kg = ks * 2;   // granule base (kw>>2), kw = ks*8
            unsigned a[4][4], b[4][2];
            #pragma unroll
            for (int mi = 0; mi < 4; mi++) {
                int row = wm + mi * 16 + lr;
                int row8 = row + 8;
                int s1 = (row >> 1) & 3, s2 = (row8 >> 1) & 3;
                a[mi][0] = As[s][row * 16 + (lq | ((kg ^ s1) << 2))];
                a[mi][1] = As[s][row8 * 16 + (lq | ((kg ^ s2) << 2))];
                a[mi][2] = As[s][row * 16 + (lq | (((kg + 1) ^ s1) << 2))];
                a[mi][3] = As[s][row8 * 16 + (lq | (((kg + 1) ^ s2) << 2))];
            }
            #pragma unroll
            for (int ni = 0; ni < 4; ni++) {
                int n = wn + ni * 8 + lr;
                int sn = (n >> 1) & 3;
                b[ni][0] = Bs[s][n * 16 + (lq | ((kg ^ sn) << 2))];
                b[ni][1] = Bs[s][n * 16 + (lq | (((kg + 1) ^ sn) << 2))];
            }
            #pragma unroll
            for (int mi = 0; mi < 4; mi++)
                #pragma unroll
                for (int ni = 0; ni < 4; ni++)
                    mma_bf16(acc[mi][ni], a[mi], b[ni]);
        }
        __syncthreads();
    }

    // ---- epilogue ----
    int m0 = blockIdx.x * 128, n0 = blockIdx.y * 128;
    #pragma unroll
    for (int mi = 0; mi < 4; mi++) {
        #pragma unroll
        for (int ni = 0; ni < 4; ni++) {
            int m = m0 + wm + mi * 16 + lr;
            int n = n0 + wn + ni * 8 + lq * 2;
            float b0 = bias ? bias[n] : 0.f;
            float b1 = bias ? bias[n + 1] : 0.f;
            float v00 = acc[mi][ni][0] + b0, v01 = acc[mi][ni][1] + b1;
            float v10 = acc[mi][ni][2] + b0, v11 = acc[mi][ni][3] + b1;
            if (OB) {
                __nv_bfloat16* Cb = (__nv_bfloat16*)Cv + (size_t)blockIdx.z * sC;
                *(__nv_bfloat162*)(Cb + (size_t)m * ldc + n) = __floats2bfloat162_rn(v00, v01);
                *(__nv_bfloat162*)(Cb + (size_t)(m + 8) * ldc + n) = __floats2bfloat162_rn(v10, v11);
            } else {
                float* Cb = (float*)Cv + (size_t)blockIdx.z * sC;
                *(float2*)(Cb + (size_t)m * ldc + n) = make_float2(v00, v01);
                *(float2*)(Cb + (size_t)(m + 8) * ldc + n) = make_float2(v10, v11);
            }
        }
    }
}

// ---------------- persistent GRU layer (writes fp32 + bf16 outputs) ----------------
__global__ __launch_bounds__(256) void gru_layer_kernel(
    const float* __restrict__ gi, const float* __restrict__ Wh,
    const float* __restrict__ bh, float* __restrict__ hout,
    __nv_bfloat16* __restrict__ houtb)
{
    __shared__ float h_s[CB * CH];
    int tid = threadIdx.x;
    for (int i = tid + blockIdx.x * 256; i < 2 * CB * CH; i += gridDim.x * 256)
        g_hbuf[i] = 0.f;
    grid_sync_all(gridDim.x);

    int warp = tid >> 5, lane = tid & 31;
    int j = blockIdx.x * 8 + warp;
    float bhr = bh[0 * CH + j], bhz = bh[1 * CH + j], bhn = bh[2 * CH + j];
    const float* Wr = Wh + (size_t)(0 * CH + j) * CH;
    const float* Wz = Wh + (size_t)(1 * CH + j) * CH;
    const float* Wn = Wh + (size_t)(2 * CH + j) * CH;

    for (int t = 0; t < CT; t++) {
        int cur = t & 1;
        const float* hsrc = g_hbuf + cur * CB * CH;
        for (int i = tid; i < CB * CH / 4; i += 256)
            ((float4*)h_s)[i] = ((const float4*)hsrc)[i];
        __syncthreads();

        float accr[CB], accz[CB], accn[CB];
        #pragma unroll
        for (int b = 0; b < CB; b++) { accr[b] = 0.f; accz[b] = 0.f; accn[b] = 0.f; }
        for (int k = lane * 4; k < CH; k += 128) {
            float4 wr = *(const float4*)(Wr + k);
            float4 wz = *(const float4*)(Wz + k);
            float4 wn = *(const float4*)(Wn + k);
            #pragma unroll
            for (int b = 0; b < CB; b++) {
                float4 hv = *(const float4*)(h_s + b * CH + k);
                accr[b] += wr.x * hv.x + wr.y * hv.y + wr.z * hv.z + wr.w * hv.w;
                accz[b] += wz.x * hv.x + wz.y * hv.y + wz.z * hv.z + wz.w * hv.w;
                accn[b] += wn.x * hv.x + wn.y * hv.y + wn.z * hv.z + wn.w * hv.w;
            }
        }
        #pragma unroll
        for (int b = 0; b < CB; b++) {
            #pragma unroll
            for (int o = 16; o; o >>= 1) {
                accr[b] += __shfl_xor_sync(0xffffffffu, accr[b], o);
                accz[b] += __shfl_xor_sync(0xffffffffu, accz[b], o);
                accn[b] += __shfl_xor_sync(0xffffffffu, accn[b], o);
            }
        }
        if (lane == 0) {
            #pragma unroll
            for (int b = 0; b < CB; b++) {
                const float* gib = gi + (size_t)(b * CT + t) * C3H;
                float ir = gib[0 * CH + j], iz = gib[1 * CH + j], inn = gib[2 * CH + j];
                float hprev = h_s[b * CH + j];
                float r = 1.f / (1.f + expf(-(ir + accr[b] + bhr)));
                float z = 1.f / (1.f + expf(-(iz + accz[b] + bhz)));
                float n = tanhf(inn + r * (accn[b] + bhn));
                float hn = (1.f - z) * n + z * hprev;
                g_hbuf[(cur ^ 1) * CB * CH + b * CH + j] = hn;
                size_t oi = (size_t)(b * CT + t) * CH + j;
                hout[oi] = hn;
                houtb[oi] = __float2bfloat16(hn);
            }
        }
        grid_sync_all(gridDim.x);
    }
}

// ---------------- small attention scores (one warp per dot) ----------------
__global__ void attn_scores_kernel(const float* __restrict__ q, const float* __restrict__ proj,
                                   float* __restrict__ out, int N) {
    int gw = (blockIdx.x * blockDim.x + threadIdx.x) >> 5;
    int lane = threadIdx.x & 31;
    if (gw >= CB * CT * N) return;
    int n = gw % N;
    int bt = gw / N;
    int b = bt / CT;
    const float* qp = q + (size_t)bt * CH;
    const float* pp = proj + (size_t)(b * N + n) * CH;
    float acc = 0.f;
    for (int k = lane * 4; k < CH; k += 128) {
        float4 qa = *(const float4*)(qp + k);
        float4 pa = *(const float4*)(pp + k);
        acc += qa.x * pa.x + qa.y * pa.y + qa.z * pa.z + qa.w * pa.w;
    }
    #pragma unroll
    for (int o = 16; o; o >>= 1) acc += __shfl_xor_sync(0xffffffffu, acc, o);
    if (lane == 0) out[gw] = acc;
}

// ---------------- fused masked softmaxes + hierarchical combine (bf16 out) ----------------
__global__ __launch_bounds__(256) void combine_kernel(
    const int* __restrict__ s_len, const int* __restrict__ u_len, const int* __restrict__ w_len,
    const int* __restrict__ seg, const int* __restrict__ utt)
{
    int bt = blockIdx.x, b = bt / CT, tid = threadIdx.x;
    __shared__ float ss[CS];
    __shared__ float su[CU];
    __shared__ float sw[CW];
    __shared__ float red[32];
    int sl = s_len[b], ul = u_len[b], wl = w_len[b];

    if (tid < 32) {
        float v = (tid < sl) ? g_sc_s[bt * CS + tid] : -INFINITY;
        float m = v;
        #pragma unroll
        for (int o = 16; o; o >>= 1) m = fmaxf(m, __shfl_xor_sync(0xffffffffu, m, o));
        float e = (tid < sl) ? expf(v - m) : 0.f;
        float s = e;
        #pragma unroll
        for (int o = 16; o; o >>= 1) s += __shfl_xor_sync(0xffffffffu, s, o);
        if (tid < CS) ss[tid] = e / s;
    }
    float uv = (tid < CU && tid < ul) ? g_sc_u[bt * CU + tid] : -INFINITY;
    float um = blockReduceMax256(uv, red);
    float ue = (tid < CU && tid < ul) ? expf(uv - um) : 0.f;
    float us = blockReduceSum256(ue, red);
    if (tid < CU) su[tid] = ue / us;
    float wv[4], we[4];
    float wm = -INFINITY;
    #pragma unroll
    for (int i = 0; i < 4; i++) {
        int idx = tid + 256 * i;
        wv[i] = (idx < wl) ? g_sc_w[(size_t)bt * CW + idx] : -INFINITY;
        wm = fmaxf(wm, wv[i]);
    }
    wm = blockReduceMax256(wm, red);
    float wsum = 0.f;
    #pragma unroll
    for (int i = 0; i < 4; i++) {
        int idx = tid + 256 * i;
        we[i] = (idx < wl) ? expf(wv[i] - wm) : 0.f;
        wsum += we[i];
    }
    wsum = blockReduceSum256(wsum, red);
    #pragma unroll
    for (int i = 0; i < 4; i++) sw[tid + 256 * i] = we[i] / wsum;
    __syncthreads();
    if (tid < CU) {
        float v2 = (tid < ul) ? ss[seg[b * CU + tid]] * su[tid] : 0.f;
        su[tid] = v2;
    }
    __syncthreads();
    float pv[4];
    #pragma unroll
    for (int i = 0; i < 4; i++) {
        int idx = tid + 256 * i;
        pv[i] = (idx < wl) ? su[utt[b * CW + idx]] * sw[idx] : 0.f;
    }
    float pm = fmaxf(fmaxf(pv[0], pv[1]), fmaxf(pv[2], pv[3]));
    pm = blockReduceMax256(pm, red);
    float pe[4];
    float psum = 0.f;
    #pragma unroll
    for (int i = 0; i < 4; i++) { pe[i] = expf(pv[i] - pm); psum += pe[i]; }
    psum = blockReduceSum256(psum, red);
    #pragma unroll
    for (int i = 0; i < 4; i++)
        gb_suw[(size_t)bt * CW + tid + 256 * i] = __float2bfloat16(pe[i] / psum);
}

// ---------------- per-batch transpose of w_output -> bf16 [B,2M,W] ----------------
__global__ void transpose_w_kernel(const float* __restrict__ wo) {
    __shared__ float tile[32][33];
    int b = blockIdx.z;
    int w0 = blockIdx.x * 32, m0 = blockIdx.y * 32;
    int x = threadIdx.x, y = threadIdx.y;
    #pragma unroll
    for (int i = 0; i < 32; i += 8)
        tile[y + i][x] = wo[((size_t)b * CW + (w0 + y + i)) * CM2 + m0 + x];
    __syncthreads();
    #pragma unroll
    for (int i = 0; i < 32; i += 8)
        gb_wT[((size_t)b * CM2 + (m0 + y + i)) * CW + w0 + x] = __float2bfloat16(tile[x][y + i]);
}

// ---------------- copy rnn (bf16) into second half of bf16 feature matrix ----------------
__global__ void copy_rnn_kernel() {
    int i = blockIdx.x * blockDim.x + threadIdx.x;
    if (i < CB * CT * CH) {
        int bt = i / CH, j = i - bt * CH;
        gb_feat[(size_t)bt * CF + CM2 + j] = gb_rnn[i];
    }
}

// ---------------- in-place log_softmax over V per (b,t) row ----------------
__global__ __launch_bounds__(256) void logsoftmax_kernel(float* __restrict__ out) {
    __shared__ float red[32];
    int row = blockIdx.x, tid = threadIdx.x;
    float* p = out + (size_t)row * CV;
    float m = -INFINITY;
    for (int i = tid; i < CV; i += 256) m = fmaxf(m, p[i]);
    m = blockReduceMax256(m, red);
    float s = 0.f;
    for (int i = tid; i < CV; i += 256) s += expf(p[i] - m);
    s = blockReduceSum256(s, red);
    float lse = m + logf(s);
    for (int i = tid; i < CV; i += 256) p[i] -= lse;
}

// ---------------- launch ----------------
extern "C" void kernel_launch(void* const* d_in, const int* in_sizes, int n_in,
                              void* d_out, int out_size) {
    const int*   target   = (const int*)d_in[0];
    const float* embedding= (const float*)d_in[1];
    const float* W_ih0    = (const float*)d_in[2];
    const float* W_hh0    = (const float*)d_in[3];
    const float* b_ih0    = (const float*)d_in[4];
    const float* b_hh0    = (const float*)d_in[5];
    const float* W_ih1    = (const float*)d_in[6];
    const float* W_hh1    = (const float*)d_in[7];
    const float* b_ih1    = (const float*)d_in[8];
    const float* b_hh1    = (const float*)d_in[9];
    const float* att_s_w  = (const float*)d_in[10];
    const float* att_s_b  = (const float*)d_in[11];
    const float* att_u_w  = (const float*)d_in[12];
    const float* att_u_b  = (const float*)d_in[13];
    const float* att_w_w  = (const float*)d_in[14];
    const float* att_w_b  = (const float*)d_in[15];
    const float* out_w    = (const float*)d_in[16];
    const float* out_b    = (const float*)d_in[17];
    const float* s_output = (const float*)d_in[18];
    const float* u_output = (const float*)d_in[19];
    const float* w_output = (const float*)d_in[20];
    const int*   s_len    = (const int*)d_in[21];
    const int*   u_len    = (const int*)d_in[22];
    const int*   w_len    = (const int*)d_in[23];
    const int*   seg      = (const int*)d_in[24];
    const int*   utt      = (const int*)d_in[25];
    float* out = (float*)d_out;

    float *p_gi, *p_h1, *p_rnn, *p_ps, *p_pu, *p_scs, *p_scu, *p_scw;
    cudaGetSymbolAddress((void**)&p_gi, g_gi);
    cudaGetSymbolAddress((void**)&p_h1, g_h1);
    cudaGetSymbolAddress((void**)&p_rnn, g_rnn);
    cudaGetSymbolAddress((void**)&p_ps, g_proj_s);
    cudaGetSymbolAddress((void**)&p_pu, g_proj_u);
    cudaGetSymbolAddress((void**)&p_scs, g_sc_s);
    cudaGetSymbolAddress((void**)&p_scu, g_sc_u);
    cudaGetSymbolAddress((void**)&p_scw, g_sc_w);
    __nv_bfloat16 *b_emb, *b_h1, *b_rnn, *b_feat, *b_suw, *b_sout, *b_uout, *b_wout,
                  *b_wT, *b_pw, *b_Wih0, *b_Wih1, *b_atts, *b_attu, *b_attw, *b_outw;
    cudaGetSymbolAddress((void**)&b_emb, gb_emb);
    cudaGetSymbolAddress((void**)&b_h1, gb_h1);
    cudaGetSymbolAddress((void**)&b_rnn, gb_rnn);
    cudaGetSymbolAddress((void**)&b_feat, gb_feat);
    cudaGetSymbolAddress((void**)&b_suw, gb_suw);
    cudaGetSymbolAddress((void**)&b_sout, gb_sout);
    cudaGetSymbolAddress((void**)&b_uout, gb_uout);
    cudaGetSymbolAddress((void**)&b_wout, gb_wout);
    cudaGetSymbolAddress((void**)&b_wT, gb_wT);
    cudaGetSymbolAddress((void**)&b_pw, gb_pw);
    cudaGetSymbolAddress((void**)&b_Wih0, gb_Wih0);
    cudaGetSymbolAddress((void**)&b_Wih1, gb_Wih1);
    cudaGetSymbolAddress((void**)&b_atts, gb_atts);
    cudaGetSymbolAddress((void**)&b_attu, gb_attu);
    cudaGetSymbolAddress((void**)&b_attw, gb_attw);
    cudaGetSymbolAddress((void**)&b_outw, gb_outw);

    // 0. convert pure-input GEMM operands to bf16
    f2b_kernel<<<(C3H * CE / 4 + 255) / 256, 256>>>(W_ih0, b_Wih0, C3H * CE);
    f2b_kernel<<<(C3H * CH / 4 + 255) / 256, 256>>>(W_ih1, b_Wih1, C3H * CH);
    f2b_kernel<<<(CH * CM / 4 + 255) / 256, 256>>>(att_s_w, b_atts, CH * CM);
    f2b_kernel<<<(CH * CM / 4 + 255) / 256, 256>>>(att_u_w, b_attu, CH * CM);
    f2b_kernel<<<(CH * CM2 / 4 + 255) / 256, 256>>>(att_w_w, b_attw, CH * CM2);
    f2b_kernel<<<(CV * CF / 4 + 255) / 256, 256>>>(out_w, b_outw, CV * CF);
    f2b_kernel<<<(CB * CS * CM / 4 + 255) / 256, 256>>>(s_output, b_sout, CB * CS * CM);
    f2b_kernel<<<(CB * CU * CM / 4 + 255) / 256, 256>>>(u_output, b_uout, CB * CU * CM);
    f2b_kernel<<<(CB * CW * CM2 / 4 + 255) / 256, 256>>>(w_output, b_wout, CB * CW * CM2);

    // 1. embedding gather (bf16)
    embed_kernel<<<(CB * CT * CE + 255) / 256, 256>>>(target, embedding);
    // 2. gi0 = emb @ W_ih0^T + b_ih0
    bgemm_nt<false><<<dim3((CB * CT) / 128, C3H / 128, 1), 256>>>(b_emb, b_Wih0, b_ih0, p_gi,
        CB * CT, C3H, CE, C3H, 0, 0, 0);
    // 3. GRU layer 0
    gru_layer_kernel<<<128, 256>>>(p_gi, W_hh0, b_hh0, p_h1, b_h1);
    // 4. gi1 = h1 @ W_ih1^T + b_ih1
    bgemm_nt<false><<<dim3((CB * CT) / 128, C3H / 128, 1), 256>>>(b_h1, b_Wih1, b_ih1, p_gi,
        CB * CT, C3H, CH, C3H, 0, 0, 0);
    // 5. GRU layer 1
    gru_layer_kernel<<<128, 256>>>(p_gi, W_hh1, b_hh1, p_rnn, b_rnn);
    // 6. attention memory projections
    bgemm_nt<false><<<dim3((CB * CS) / 128, CH / 128, 1), 256>>>(b_sout, b_atts, att_s_b, p_ps,
        CB * CS, CH, CM, CH, 0, 0, 0);
    bgemm_nt<false><<<dim3((CB * CU) / 128, CH / 128, 1), 256>>>(b_uout, b_attu, att_u_b, p_pu,
        CB * CU, CH, CM, CH, 0, 0, 0);
    bgemm_nt<true><<<dim3((CB * CW) / 128, CH / 128, 1), 256>>>(b_wout, b_attw, att_w_b, b_pw,
        CB * CW, CH, CM2, CH, 0, 0, 0);
    // 7. raw scores
    attn_scores_kernel<<<(CB * CT * CS) / 8, 256>>>(p_rnn, p_ps, p_scs, CS);
    attn_scores_kernel<<<(CB * CT * CU) / 8, 256>>>(p_rnn, p_pu, p_scu, CU);
    bgemm_nt<false><<<dim3(CT / 128, CW / 128, CB), 256>>>(b_rnn, b_pw, nullptr, p_scw,
        CT, CW, CH, CW, (long)CT * CH, (long)CW * CH, (long)CT * CW);
    // 8. masked softmaxes + hierarchical combine + final softmax (bf16 out)
    combine_kernel<<<CB * CT, 256>>>(s_len, u_len, w_len, seg, utt);
    // 9. context = suw @ w_output -> bf16 feat[:, :1024]
    transpose_w_kernel<<<dim3(CW / 32, CM2 / 32, CB), dim3(32, 8)>>>(w_output);
    bgemm_nt<true><<<dim3(CT / 128, CM2 / 128, CB), 256>>>(b_suw, b_wT, nullptr, b_feat,
        CT, CM2, CW, CF, (long)CT * CW, (long)CM2 * CW, (long)CT * CF);
    // 10. feat[:, 1024:2048] = rnn (bf16)
    copy_rnn_kernel<<<(CB * CT * CH + 255) / 256, 256>>>();
    // 11. logits = feat @ out_w^T + out_b -> d_out (fp32)
    bgemm_nt<false><<<dim3((CB * CT) / 128, CV / 128, 1), 256>>>(b_feat, b_outw, out_b, out,
        CB * CT, CV, CF, CV, 0, 0, 0);
    // 12. in-place log_softmax
    logsoftmax_kernel<<<CB * CT, 256>>>(out);
}

// round 8
// speedup vs baseline: 2.2614x; 1.0213x over previous
#include <cuda_runtime.h>
#include <cuda_bf16.h>
#include <math.h>

// ---------------- problem constants ----------------
#define CB 8       // batch
#define CT 128     // time
#define CE 512     // embed dim
#define CH 1024    // hidden
#define CM 512     // mem hidden
#define CM2 1024   // 2*M
#define CS 16
#define CU 128
#define CW 1024
#define CV 32000
#define C3H 3072
#define CF 2048    // H + 2M

// ---------------- fp32 scratch ----------------
__device__ float g_gi[CB * CT * C3H];
__device__ float g_h1[CB * CT * CH];
__device__ float g_rnn[CB * CT * CH];
__device__ float g_hbuf[2 * CB * CH];
__device__ float g_proj_s[CB * CS * CH];
__device__ float g_proj_u[CB * CU * CH];
__device__ float g_sc_s[CB * CT * CS];
__device__ float g_sc_u[CB * CT * CU];
__device__ float g_sc_w[CB * CT * CW];
__device__ unsigned g_bar_arr = 0;
__device__ unsigned g_bar_gen = 0;

// ---------------- bf16 scratch (GEMM operands) ----------------
__device__ __nv_bfloat16 gb_emb[CB * CT * CE];
__device__ __nv_bfloat16 gb_h1[CB * CT * CH];
__device__ __nv_bfloat16 gb_feat[CB * CT * CF];
__device__ __nv_bfloat16 gb_suw[CB * CT * CW];
__device__ __nv_bfloat16 gb_sout[CB * CS * CM];
__device__ __nv_bfloat16 gb_uout[CB * CU * CM];
__device__ __nv_bfloat16 gb_wout[CB * CW * CM2];
__device__ __nv_bfloat16 gb_wT[CB * CM2 * CW];
__device__ __nv_bfloat16 gb_pw[CB * CW * CH];
__device__ __nv_bfloat16 gb_Wih0[C3H * CE];
__device__ __nv_bfloat16 gb_Wih1[C3H * CH];
__device__ __nv_bfloat16 gb_atts[CH * CM];
__device__ __nv_bfloat16 gb_attu[CH * CM];
__device__ __nv_bfloat16 gb_attw[CH * CM2];
__device__ __nv_bfloat16 gb_outw[(size_t)CV * CF];   // 131 MB

// ---------------- grid barrier (persistent GRU kernel) ----------------
__device__ __forceinline__ void grid_sync_all(unsigned nb) {
    __threadfence();
    __syncthreads();
    if (threadIdx.x == 0) {
        unsigned gen = atomicAdd(&g_bar_gen, 0u);
        if (atomicAdd(&g_bar_arr, 1u) == nb - 1u) {
            atomicExch(&g_bar_arr, 0u);
            __threadfence();
            atomicAdd(&g_bar_gen, 1u);
        } else {
            while (atomicAdd(&g_bar_gen, 0u) == gen) { __nanosleep(64); }
        }
    }
    __syncthreads();
}

// ---------------- block reductions (256 threads fixed) ----------------
__device__ __forceinline__ float blockReduceMax256(float v, float* red) {
    #pragma unroll
    for (int o = 16; o; o >>= 1) v = fmaxf(v, __shfl_xor_sync(0xffffffffu, v, o));
    if ((threadIdx.x & 31) == 0) red[threadIdx.x >> 5] = v;
    __syncthreads();
    if (threadIdx.x < 32) {
        float r = (threadIdx.x < 8) ? red[threadIdx.x] : -INFINITY;
        #pragma unroll
        for (int o = 4; o; o >>= 1) r = fmaxf(r, __shfl_xor_sync(0xffffffffu, r, o));
        if (threadIdx.x == 0) red[0] = r;
    }
    __syncthreads();
    float out = red[0];
    __syncthreads();
    return out;
}

__device__ __forceinline__ float blockReduceSum256(float v, float* red) {
    #pragma unroll
    for (int o = 16; o; o >>= 1) v += __shfl_xor_sync(0xffffffffu, v, o);
    if ((threadIdx.x & 31) == 0) red[threadIdx.x >> 5] = v;
    __syncthreads();
    if (threadIdx.x < 32) {
        float r = (threadIdx.x < 8) ? red[threadIdx.x] : 0.f;
        #pragma unroll
        for (int o = 4; o; o >>= 1) r += __shfl_xor_sync(0xffffffffu, r, o);
        if (threadIdx.x == 0) red[0] = r;
    }
    __syncthreads();
    float out = red[0];
    __syncthreads();
    return out;
}

// ---------------- fp32 -> bf16 convert ----------------
__global__ void f2b_kernel(const float* __restrict__ src, __nv_bfloat16* __restrict__ dst, int n) {
    int i = (blockIdx.x * blockDim.x + threadIdx.x) * 4;
    if (i < n) {
        float4 v = *(const float4*)(src + i);
        __nv_bfloat162* d = (__nv_bfloat162*)(dst + i);
        d[0] = __floats2bfloat162_rn(v.x, v.y);
        d[1] = __floats2bfloat162_rn(v.z, v.w);
    }
}

// ---------------- embedding gather (writes bf16 directly) ----------------
__global__ void embed_kernel(const int* __restrict__ target, const float* __restrict__ emb) {
    int i = blockIdx.x * blockDim.x + threadIdx.x;
    if (i < CB * CT * CE) {
        int bt = i / CE, e = i - bt * CE;
        gb_emb[i] = __float2bfloat16(emb[(size_t)target[bt] * CE + e]);
    }
}

// ---------------- mma / ldmatrix / cp.async helpers ----------------
__device__ __forceinline__ void mma_bf16(float* d, const unsigned* a, const unsigned* b) {
    asm volatile(
        "mma.sync.aligned.m16n8k16.row.col.f32.bf16.bf16.f32 "
        "{%0,%1,%2,%3}, {%4,%5,%6,%7}, {%8,%9}, {%0,%1,%2,%3};"
        : "+f"(d[0]), "+f"(d[1]), "+f"(d[2]), "+f"(d[3])
        : "r"(a[0]), "r"(a[1]), "r"(a[2]), "r"(a[3]), "r"(b[0]), "r"(b[1]));
}

__device__ __forceinline__ void ldsm4(unsigned& r0, unsigned& r1, unsigned& r2, unsigned& r3,
                                      unsigned addr) {
    asm volatile("ldmatrix.sync.aligned.m8n8.x4.shared.b16 {%0,%1,%2,%3}, [%4];"
        : "=r"(r0), "=r"(r1), "=r"(r2), "=r"(r3) : "r"(addr));
}

__device__ __forceinline__ void cpa16(unsigned dst, const void* src) {
    asm volatile("cp.async.ca.shared.global [%0], [%1], 16;" :: "r"(dst), "l"(src));
}

// ---------------- bf16 tensor-core NT GEMM, 3-stage cp.async + ldmatrix ----------------
// C[m,n] = A[m,:].B[n,:] + bias[n].  A:[M,K] bf16 (row stride lda), B:[N,K] bf16 (ldb).
// Block tile 128x128, KT=32, 3 smem stages. 8 warps (2M x 4N), warp tile 64x32.
// Smem swizzle: byte = row*64 + ((g ^ ((row>>1)&3))<<4), g = 16B granule (k/8).
// Conflict-free for cp.async stores, and for ldmatrix (8 rows/phase hit distinct
// 16B bank groups). Requires M%128==0, N%128==0, K%32==0, K>=64.
template<bool OB>
__global__ __launch_bounds__(256, 2) void bgemm_nt(
    const __nv_bfloat16* __restrict__ A, const __nv_bfloat16* __restrict__ Bm,
    const float* __restrict__ bias, void* __restrict__ Cv,
    int K, int lda, int ldb, int ldc, long sA, long sB, long sC)
{
    __shared__ unsigned As[3][2048];   // 3 x 8 KB
    __shared__ unsigned Bs[3][2048];   // 3 x 8 KB
    const __nv_bfloat16* Ab = A + (size_t)blockIdx.z * sA + (size_t)(blockIdx.x * 128) * lda;
    const __nv_bfloat16* Bb = Bm + (size_t)blockIdx.z * sB + (size_t)(blockIdx.y * 128) * ldb;
    int tid = threadIdx.x;
    int warp = tid >> 5, lane = tid & 31;
    int wm = (warp >> 2) * 64, wn = (warp & 3) * 32;
    int lr = lane >> 2, lq = lane & 3;

    // staging: thread -> rows (r0, r0+64), granule g0. Same swizzle for row+64.
    int r0 = tid >> 2, g0 = tid & 3;
    unsigned woff = (unsigned)(r0 * 64 + ((g0 ^ ((r0 >> 1) & 3)) << 4));
    unsigned baseA = (unsigned)__cvta_generic_to_shared(&As[0][0]);
    unsigned baseB = (unsigned)__cvta_generic_to_shared(&Bs[0][0]);
    const __nv_bfloat16* srcA0 = Ab + (size_t)r0 * lda + g0 * 8;
    const __nv_bfloat16* srcA1 = srcA0 + (size_t)64 * lda;
    const __nv_bfloat16* srcB0 = Bb + (size_t)r0 * ldb + g0 * 8;
    const __nv_bfloat16* srcB1 = srcB0 + (size_t)64 * ldb;

    // ldmatrix lane geometry
    int lt = lane >> 3, rr = lane & 7;
    // A: x4 tiles = (rows+0, kg), (rows+8, kg), (rows+0, kg+1), (rows+8, kg+1)
    int gAoff = lt >> 1;
    unsigned rowA64[4]; unsigned swzA[4];
    #pragma unroll
    for (int mi = 0; mi < 4; mi++) {
        int row = wm + mi * 16 + ((lt & 1) << 3) + rr;
        rowA64[mi] = row * 64;
        swzA[mi] = (row >> 1) & 3;
    }
    // B: x4 tiles = (ni2, kg), (ni2, kg+1), (ni2+1, kg), (ni2+1, kg+1)
    int gBoff = lt & 1;
    unsigned rowB64[2]; unsigned swzB[2];
    #pragma unroll
    for (int np = 0; np < 2; np++) {
        int row = wn + np * 16 + ((lt >> 1) << 3) + rr;
        rowB64[np] = row * 64;
        swzB[np] = (row >> 1) & 3;
    }

    float acc[4][4][4];
    #pragma unroll
    for (int mi = 0; mi < 4; mi++)
        #pragma unroll
        for (int ni = 0; ni < 4; ni++)
            #pragma unroll
            for (int r = 0; r < 4; r++) acc[mi][ni][r] = 0.f;

#define STAGE_LOAD(st, kt) do { \
        cpa16(baseA + (st) * 8192 + woff, srcA0 + (kt)); \
        cpa16(baseA + (st) * 8192 + woff + 4096, srcA1 + (kt)); \
        cpa16(baseB + (st) * 8192 + woff, srcB0 + (kt)); \
        cpa16(baseB + (st) * 8192 + woff + 4096, srcB1 + (kt)); \
        asm volatile("cp.async.commit_group;"); } while (0)

    int nt = K / 32;
    STAGE_LOAD(0, 0);
    STAGE_LOAD(1, 32);

    for (int it = 0; it < nt; it++) {
        if (it + 1 < nt) asm volatile("cp.async.wait_group 1;");
        else             asm volatile("cp.async.wait_group 0;");
        __syncthreads();
        if (it + 2 < nt) STAGE_LOAD((it + 2) % 3, (it + 2) * 32);

        int s = it % 3;
        unsigned stA = baseA + s * 8192;
        unsigned stB = baseB + s * 8192;
        #pragma unroll
        for (int ks = 0; ks < 2; ks++) {
            const int kg = ks * 2;
            unsigned a[4][4], b[4][2];
            #pragma unroll
            for (int mi = 0; mi < 4; mi++)
                ldsm4(a[mi][0], a[mi][1], a[mi][2], a[mi][3],
                      stA + rowA64[mi] + ((unsigned)((kg + gAoff) ^ swzA[mi]) << 4));
            #pragma unroll
            for (int np = 0; np < 2; np++)
                ldsm4(b[2 * np][0], b[2 * np][1], b[2 * np + 1][0], b[2 * np + 1][1],
                      stB + rowB64[np] + ((unsigned)((kg + gBoff) ^ swzB[np]) << 4));
            #pragma unroll
            for (int mi = 0; mi < 4; mi++)
                #pragma unroll
                for (int ni = 0; ni < 4; ni++)
                    mma_bf16(acc[mi][ni], a[mi], b[ni]);
        }
        // no trailing sync: next iter's barrier precedes the overwrite of this stage
    }
#undef STAGE_LOAD

    // ---- epilogue ----
    int m0 = blockIdx.x * 128, n0 = blockIdx.y * 128;
    #pragma unroll
    for (int mi = 0; mi < 4; mi++) {
        #pragma unroll
        for (int ni = 0; ni < 4; ni++) {
            int m = m0 + wm + mi * 16 + lr;
            int n = n0 + wn + ni * 8 + lq * 2;
            float b0 = bias ? bias[n] : 0.f;
            float b1 = bias ? bias[n + 1] : 0.f;
            float v00 = acc[mi][ni][0] + b0, v01 = acc[mi][ni][1] + b1;
            float v10 = acc[mi][ni][2] + b0, v11 = acc[mi][ni][3] + b1;
            if (OB) {
                __nv_bfloat16* Cb = (__nv_bfloat16*)Cv + (size_t)blockIdx.z * sC;
                *(__nv_bfloat162*)(Cb + (size_t)m * ldc + n) = __floats2bfloat162_rn(v00, v01);
                *(__nv_bfloat162*)(Cb + (size_t)(m + 8) * ldc + n) = __floats2bfloat162_rn(v10, v11);
            } else {
                float* Cb = (float*)Cv + (size_t)blockIdx.z * sC;
                *(float2*)(Cb + (size_t)m * ldc + n) = make_float2(v00, v01);
                *(float2*)(Cb + (size_t)(m + 8) * ldc + n) = make_float2(v10, v11);
            }
        }
    }
}

// ---------------- persistent GRU layer (writes fp32 + strided bf16 outputs) ----------------
__global__ __launch_bounds__(256) void gru_layer_kernel(
    const float* __restrict__ gi, const float* __restrict__ Wh,
    const float* __restrict__ bh, float* __restrict__ hout,
    __nv_bfloat16* __restrict__ houtb, int ldo)
{
    __shared__ float h_s[CB * CH];
    int tid = threadIdx.x;
    for (int i = tid + blockIdx.x * 256; i < 2 * CB * CH; i += gridDim.x * 256)
        g_hbuf[i] = 0.f;
    grid_sync_all(gridDim.x);

    int warp = tid >> 5, lane = tid & 31;
    int j = blockIdx.x * 8 + warp;
    float bhr = bh[0 * CH + j], bhz = bh[1 * CH + j], bhn = bh[2 * CH + j];
    const float* Wr = Wh + (size_t)(0 * CH + j) * CH;
    const float* Wz = Wh + (size_t)(1 * CH + j) * CH;
    const float* Wn = Wh + (size_t)(2 * CH + j) * CH;

    for (int t = 0; t < CT; t++) {
        int cur = t & 1;
        const float* hsrc = g_hbuf + cur * CB * CH;
        for (int i = tid; i < CB * CH / 4; i += 256)
            ((float4*)h_s)[i] = ((const float4*)hsrc)[i];
        __syncthreads();

        float accr[CB], accz[CB], accn[CB];
        #pragma unroll
        for (int b = 0; b < CB; b++) { accr[b] = 0.f; accz[b] = 0.f; accn[b] = 0.f; }
        for (int k = lane * 4; k < CH; k += 128) {
            float4 wr = *(const float4*)(Wr + k);
            float4 wz = *(const float4*)(Wz + k);
            float4 wn = *(const float4*)(Wn + k);
            #pragma unroll
            for (int b = 0; b < CB; b++) {
                float4 hv = *(const float4*)(h_s + b * CH + k);
                accr[b] += wr.x * hv.x + wr.y * hv.y + wr.z * hv.z + wr.w * hv.w;
                accz[b] += wz.x * hv.x + wz.y * hv.y + wz.z * hv.z + wz.w * hv.w;
                accn[b] += wn.x * hv.x + wn.y * hv.y + wn.z * hv.z + wn.w * hv.w;
            }
        }
        #pragma unroll
        for (int b = 0; b < CB; b++) {
            #pragma unroll
            for (int o = 16; o; o >>= 1) {
                accr[b] += __shfl_xor_sync(0xffffffffu, accr[b], o);
                accz[b] += __shfl_xor_sync(0xffffffffu, accz[b], o);
                accn[b] += __shfl_xor_sync(0xffffffffu, accn[b], o);
            }
        }
        if (lane == 0) {
            #pragma unroll
            for (int b = 0; b < CB; b++) {
                const float* gib = gi + (size_t)(b * CT + t) * C3H;
                float ir = gib[0 * CH + j], iz = gib[1 * CH + j], inn = gib[2 * CH + j];
                float hprev = h_s[b * CH + j];
                float r = 1.f / (1.f + expf(-(ir + accr[b] + bhr)));
                float z = 1.f / (1.f + expf(-(iz + accz[b] + bhz)));
                float n = tanhf(inn + r * (accn[b] + bhn));
                float hn = (1.f - z) * n + z * hprev;
                g_hbuf[(cur ^ 1) * CB * CH + b * CH + j] = hn;
                hout[(size_t)(b * CT + t) * CH + j] = hn;
                houtb[(size_t)(b * CT + t) * ldo + j] = __float2bfloat16(hn);
            }
        }
        grid_sync_all(gridDim.x);
    }
}

// ---------------- small attention scores (one warp per dot) ----------------
__global__ void attn_scores_kernel(const float* __restrict__ q, const float* __restrict__ proj,
                                   float* __restrict__ out, int N) {
    int gw = (blockIdx.x * blockDim.x + threadIdx.x) >> 5;
    int lane = threadIdx.x & 31;
    if (gw >= CB * CT * N) return;
    int n = gw % N;
    int bt = gw / N;
    int b = bt / CT;
    const float* qp = q + (size_t)bt * CH;
    const float* pp = proj + (size_t)(b * N + n) * CH;
    float acc = 0.f;
    for (int k = lane * 4; k < CH; k += 128) {
        float4 qa = *(const float4*)(qp + k);
        float4 pa = *(const float4*)(pp + k);
        acc += qa.x * pa.x + qa.y * pa.y + qa.z * pa.z + qa.w * pa.w;
    }
    #pragma unroll
    for (int o = 16; o; o >>= 1) acc += __shfl_xor_sync(0xffffffffu, acc, o);
    if (lane == 0) out[gw] = acc;
}

// ---------------- fused masked softmaxes + hierarchical combine (bf16 out) ----------------
__global__ __launch_bounds__(256) void combine_kernel(
    const int* __restrict__ s_len, const int* __restrict__ u_len, const int* __restrict__ w_len,
    const int* __restrict__ seg, const int* __restrict__ utt)
{
    int bt = blockIdx.x, b = bt / CT, tid = threadIdx.x;
    __shared__ float ss[CS];
    __shared__ float su[CU];
    __shared__ float sw[CW];
    __shared__ float red[32];
    int sl = s_len[b], ul = u_len[b], wl = w_len[b];

    if (tid < 32) {
        float v = (tid < sl) ? g_sc_s[bt * CS + tid] : -INFINITY;
        float m = v;
        #pragma unroll
        for (int o = 16; o; o >>= 1) m = fmaxf(m, __shfl_xor_sync(0xffffffffu, m, o));
        float e = (tid < sl) ? expf(v - m) : 0.f;
        float s = e;
        #pragma unroll
        for (int o = 16; o; o >>= 1) s += __shfl_xor_sync(0xffffffffu, s, o);
        if (tid < CS) ss[tid] = e / s;
    }
    float uv = (tid < CU && tid < ul) ? g_sc_u[bt * CU + tid] : -INFINITY;
    float um = blockReduceMax256(uv, red);
    float ue = (tid < CU && tid < ul) ? expf(uv - um) : 0.f;
    float us = blockReduceSum256(ue, red);
    if (tid < CU) su[tid] = ue / us;
    float wv[4], we[4];
    float wm = -INFINITY;
    #pragma unroll
    for (int i = 0; i < 4; i++) {
        int idx = tid + 256 * i;
        wv[i] = (idx < wl) ? g_sc_w[(size_t)bt * CW + idx] : -INFINITY;
        wm = fmaxf(wm, wv[i]);
    }
    wm = blockReduceMax256(wm, red);
    float wsum = 0.f;
    #pragma unroll
    for (int i = 0; i < 4; i++) {
        int idx = tid + 256 * i;
        we[i] = (idx < wl) ? expf(wv[i] - wm) : 0.f;
        wsum += we[i];
    }
    wsum = blockReduceSum256(wsum, red);
    #pragma unroll
    for (int i = 0; i < 4; i++) sw[tid + 256 * i] = we[i] / wsum;
    __syncthreads();
    if (tid < CU) {
        float v2 = (tid < ul) ? ss[seg[b * CU + tid]] * su[tid] : 0.f;
        su[tid] = v2;
    }
    __syncthreads();
    float pv[4];
    #pragma unroll
    for (int i = 0; i < 4; i++) {
        int idx = tid + 256 * i;
        pv[i] = (idx < wl) ? su[utt[b * CW + idx]] * sw[idx] : 0.f;
    }
    float pm = fmaxf(fmaxf(pv[0], pv[1]), fmaxf(pv[2], pv[3]));
    pm = blockReduceMax256(pm, red);
    float pe[4];
    float psum = 0.f;
    #pragma unroll
    for (int i = 0; i < 4; i++) { pe[i] = expf(pv[i] - pm); psum += pe[i]; }
    psum = blockReduceSum256(psum, red);
    #pragma unroll
    for (int i = 0; i < 4; i++)
        gb_suw[(size_t)bt * CW + tid + 256 * i] = __float2bfloat16(pe[i] / psum);
}

// ---------------- per-batch transpose of w_output -> bf16 [B,2M,W] ----------------
__global__ void transpose_w_kernel(const float* __restrict__ wo) {
    __shared__ float tile[32][33];
    int b = blockIdx.z;
    int w0 = blockIdx.x * 32, m0 = blockIdx.y * 32;
    int x = threadIdx.x, y = threadIdx.y;
    #pragma unroll
    for (int i = 0; i < 32; i += 8)
        tile[y + i][x] = wo[((size_t)b * CW + (w0 + y + i)) * CM2 + m0 + x];
    __syncthreads();
    #pragma unroll
    for (int i = 0; i < 32; i += 8)
        gb_wT[((size_t)b * CM2 + (m0 + y + i)) * CW + w0 + x] = __float2bfloat16(tile[x][y + i]);
}

// ---------------- in-place log_softmax over V per (b,t) row ----------------
__global__ __launch_bounds__(256) void logsoftmax_kernel(float* __restrict__ out) {
    __shared__ float red[32];
    int row = blockIdx.x, tid = threadIdx.x;
    float* p = out + (size_t)row * CV;
    float m = -INFINITY;
    for (int i = tid; i < CV; i += 256) m = fmaxf(m, p[i]);
    m = blockReduceMax256(m, red);
    float s = 0.f;
    for (int i = tid; i < CV; i += 256) s += expf(p[i] - m);
    s = blockReduceSum256(s, red);
    float lse = m + logf(s);
    for (int i = tid; i < CV; i += 256) p[i] -= lse;
}

// ---------------- launch ----------------
extern "C" void kernel_launch(void* const* d_in, const int* in_sizes, int n_in,
                              void* d_out, int out_size) {
    const int*   target   = (const int*)d_in[0];
    const float* embedding= (const float*)d_in[1];
    const float* W_ih0    = (const float*)d_in[2];
    const float* W_hh0    = (const float*)d_in[3];
    const float* b_ih0    = (const float*)d_in[4];
    const float* b_hh0    = (const float*)d_in[5];
    const float* W_ih1    = (const float*)d_in[6];
    const float* W_hh1    = (const float*)d_in[7];
    const float* b_ih1    = (const float*)d_in[8];
    const float* b_hh1    = (const float*)d_in[9];
    const float* att_s_w  = (const float*)d_in[10];
    const float* att_s_b  = (const float*)d_in[11];
    const float* att_u_w  = (const float*)d_in[12];
    const float* att_u_b  = (const float*)d_in[13];
    const float* att_w_w  = (const float*)d_in[14];
    const float* att_w_b  = (const float*)d_in[15];
    const float* out_w    = (const float*)d_in[16];
    const float* out_b    = (const float*)d_in[17];
    const float* s_output = (const float*)d_in[18];
    const float* u_output = (const float*)d_in[19];
    const float* w_output = (const float*)d_in[20];
    const int*   s_len    = (const int*)d_in[21];
    const int*   u_len    = (const int*)d_in[22];
    const int*   w_len    = (const int*)d_in[23];
    const int*   seg      = (const int*)d_in[24];
    const int*   utt      = (const int*)d_in[25];
    float* out = (float*)d_out;

    float *p_gi, *p_h1, *p_rnn, *p_ps, *p_pu, *p_scs, *p_scu, *p_scw;
    cudaGetSymbolAddress((void**)&p_gi, g_gi);
    cudaGetSymbolAddress((void**)&p_h1, g_h1);
    cudaGetSymbolAddress((void**)&p_rnn, g_rnn);
    cudaGetSymbolAddress((void**)&p_ps, g_proj_s);
    cudaGetSymbolAddress((void**)&p_pu, g_proj_u);
    cudaGetSymbolAddress((void**)&p_scs, g_sc_s);
    cudaGetSymbolAddress((void**)&p_scu, g_sc_u);
    cudaGetSymbolAddress((void**)&p_scw, g_sc_w);
    __nv_bfloat16 *b_emb, *b_h1, *b_feat, *b_suw, *b_sout, *b_uout, *b_wout,
                  *b_wT, *b_pw, *b_Wih0, *b_Wih1, *b_atts, *b_attu, *b_attw, *b_outw;
    cudaGetSymbolAddress((void**)&b_emb, gb_emb);
    cudaGetSymbolAddress((void**)&b_h1, gb_h1);
    cudaGetSymbolAddress((void**)&b_feat, gb_feat);
    cudaGetSymbolAddress((void**)&b_suw, gb_suw);
    cudaGetSymbolAddress((void**)&b_sout, gb_sout);
    cudaGetSymbolAddress((void**)&b_uout, gb_uout);
    cudaGetSymbolAddress((void**)&b_wout, gb_wout);
    cudaGetSymbolAddress((void**)&b_wT, gb_wT);
    cudaGetSymbolAddress((void**)&b_pw, gb_pw);
    cudaGetSymbolAddress((void**)&b_Wih0, gb_Wih0);
    cudaGetSymbolAddress((void**)&b_Wih1, gb_Wih1);
    cudaGetSymbolAddress((void**)&b_atts, gb_atts);
    cudaGetSymbolAddress((void**)&b_attu, gb_attu);
    cudaGetSymbolAddress((void**)&b_attw, gb_attw);
    cudaGetSymbolAddress((void**)&b_outw, gb_outw);

    // 0. convert pure-input GEMM operands to bf16
    f2b_kernel<<<(C3H * CE / 4 + 255) / 256, 256>>>(W_ih0, b_Wih0, C3H * CE);
    f2b_kernel<<<(C3H * CH / 4 + 255) / 256, 256>>>(W_ih1, b_Wih1, C3H * CH);
    f2b_kernel<<<(CH * CM / 4 + 255) / 256, 256>>>(att_s_w, b_atts, CH * CM);
    f2b_kernel<<<(CH * CM / 4 + 255) / 256, 256>>>(att_u_w, b_attu, CH * CM);
    f2b_kernel<<<(CH * CM2 / 4 + 255) / 256, 256>>>(att_w_w, b_attw, CH * CM2);
    f2b_kernel<<<(CV * CF / 4 + 255) / 256, 256>>>(out_w, b_outw, CV * CF);
    f2b_kernel<<<(CB * CS * CM / 4 + 255) / 256, 256>>>(s_output, b_sout, CB * CS * CM);
    f2b_kernel<<<(CB * CU * CM / 4 + 255) / 256, 256>>>(u_output, b_uout, CB * CU * CM);
    f2b_kernel<<<(CB * CW * CM2 / 4 + 255) / 256, 256>>>(w_output, b_wout, CB * CW * CM2);

    // 1. embedding gather (bf16)
    embed_kernel<<<(CB * CT * CE + 255) / 256, 256>>>(target, embedding);
    // 2. gi0 = emb @ W_ih0^T + b_ih0
    bgemm_nt<false><<<dim3((CB * CT) / 128, C3H / 128, 1), 256>>>(b_emb, b_Wih0, b_ih0, p_gi,
        CE, CE, CE, C3H, 0, 0, 0);
    // 3. GRU layer 0 -> fp32 h1 + bf16 gb_h1
    gru_layer_kernel<<<128, 256>>>(p_gi, W_hh0, b_hh0, p_h1, b_h1, CH);
    // 4. gi1 = h1 @ W_ih1^T + b_ih1
    bgemm_nt<false><<<dim3((CB * CT) / 128, C3H / 128, 1), 256>>>(b_h1, b_Wih1, b_ih1, p_gi,
        CH, CH, CH, C3H, 0, 0, 0);
    // 5. GRU layer 1 -> fp32 rnn + bf16 directly into feat[:, 1024:]
    gru_layer_kernel<<<128, 256>>>(p_gi, W_hh1, b_hh1, p_rnn, b_feat + CM2, CF);
    // 6. attention memory projections
    bgemm_nt<false><<<dim3((CB * CS) / 128, CH / 128, 1), 256>>>(b_sout, b_atts, att_s_b, p_ps,
        CM, CM, CM, CH, 0, 0, 0);
    bgemm_nt<false><<<dim3((CB * CU) / 128, CH / 128, 1), 256>>>(b_uout, b_attu, att_u_b, p_pu,
        CM, CM, CM, CH, 0, 0, 0);
    bgemm_nt<true><<<dim3((CB * CW) / 128, CH / 128, 1), 256>>>(b_wout, b_attw, att_w_b, b_pw,
        CM2, CM2, CM2, CH, 0, 0, 0);
    // 7. raw scores
    attn_scores_kernel<<<(CB * CT * CS) / 8, 256>>>(p_rnn, p_ps, p_scs, CS);
    attn_scores_kernel<<<(CB * CT * CU) / 8, 256>>>(p_rnn, p_pu, p_scu, CU);
    bgemm_nt<false><<<dim3(CT / 128, CW / 128, CB), 256>>>(b_feat + CM2, b_pw, nullptr, p_scw,
        CH, CF, CH, CW, (long)CT * CF, (long)CW * CH, (long)CT * CW);
    // 8. masked softmaxes + hierarchical combine + final softmax (bf16 out)
    combine_kernel<<<CB * CT, 256>>>(s_len, u_len, w_len, seg, utt);
    // 9. context = suw @ w_output -> bf16 feat[:, :1024]
    transpose_w_kernel<<<dim3(CW / 32, CM2 / 32, CB), dim3(32, 8)>>>(w_output);
    bgemm_nt<true><<<dim3(CT / 128, CM2 / 128, CB), 256>>>(b_suw, b_wT, nullptr, b_feat,
        CW, CW, CW, CF, (long)CT * CW, (long)CM2 * CW, (long)CT * CF);
    // 10. logits = feat @ out_w^T + out_b -> d_out (fp32)
    bgemm_nt<false><<<dim3((CB * CT) / 128, CV / 128, 1), 256>>>(b_feat, b_outw, out_b, out,
        CF, CF, CF, CV, 0, 0, 0);
    // 11. in-place log_softmax
    logsoftmax_kernel<<<CB * CT, 256>>>(out);
}

// round 10
// speedup vs baseline: 3.5043x; 1.5496x over previous
#include <cuda_runtime.h>
#include <cuda_bf16.h>
#include <math.h>

// ---------------- problem constants ----------------
#define CB 8       // batch
#define CT 128     // time
#define CE 512     // embed dim
#define CH 1024    // hidden
#define CM 512     // mem hidden
#define CM2 1024   // 2*M
#define CS 16
#define CU 128
#define CW 1024
#define CV 32000
#define C3H 3072
#define CF 2048    // H + 2M

// ---------------- fp32 scratch ----------------
__device__ float g_gi[CB * CT * C3H];
__device__ float g_rnn[CB * CT * CH];
__device__ float g_proj_s[CB * CS * CH];
__device__ float g_proj_u[CB * CU * CH];
__device__ float g_sc_s[CB * CT * CS];
__device__ float g_sc_u[CB * CT * CU];
__device__ float g_sc_w[CB * CT * CW];
__device__ unsigned g_bar_arr = 0;
__device__ unsigned g_bar_gen = 0;

// ---------------- bf16 scratch ----------------
__device__ __nv_bfloat16 gb_emb[CB * CT * CE];
__device__ __nv_bfloat16 gb_h1[CB * CT * CH];
__device__ __nv_bfloat16 gb_feat[CB * CT * CF];
__device__ __nv_bfloat16 gb_suw[CB * CT * CW];
__device__ __nv_bfloat16 gb_sout[CB * CS * CM];
__device__ __nv_bfloat16 gb_uout[CB * CU * CM];
__device__ __nv_bfloat16 gb_wout[CB * CW * CM2];
__device__ __nv_bfloat16 gb_wT[CB * CM2 * CW];
__device__ __nv_bfloat16 gb_pw[CB * CW * CH];
__device__ __nv_bfloat16 gb_Wih0[C3H * CE];
__device__ __nv_bfloat16 gb_Wih1[C3H * CH];
__device__ __nv_bfloat16 gb_atts[CH * CM];
__device__ __nv_bfloat16 gb_attu[CH * CM];
__device__ __nv_bfloat16 gb_attw[CH * CM2];
__device__ __nv_bfloat16 gb_outw[(size_t)CV * CF];   // 131 MB
__device__ __nv_bfloat16 g_hbf[2][CB * CH];          // GRU h broadcast (double buffer)

// ---------------- grid barrier ----------------
__device__ __forceinline__ void grid_sync_all(unsigned nb) {
    __threadfence();
    __syncthreads();
    if (threadIdx.x == 0) {
        unsigned gen = atomicAdd(&g_bar_gen, 0u);
        if (atomicAdd(&g_bar_arr, 1u) == nb - 1u) {
            atomicExch(&g_bar_arr, 0u);
            __threadfence();
            atomicAdd(&g_bar_gen, 1u);
        } else {
            while (atomicAdd(&g_bar_gen, 0u) == gen) { __nanosleep(32); }
        }
    }
    __syncthreads();
}

// ---------------- block reductions (256 threads) ----------------
__device__ __forceinline__ float blockReduceMax256(float v, float* red) {
    #pragma unroll
    for (int o = 16; o; o >>= 1) v = fmaxf(v, __shfl_xor_sync(0xffffffffu, v, o));
    if ((threadIdx.x & 31) == 0) red[threadIdx.x >> 5] = v;
    __syncthreads();
    if (threadIdx.x < 32) {
        float r = (threadIdx.x < 8) ? red[threadIdx.x] : -INFINITY;
        #pragma unroll
        for (int o = 4; o; o >>= 1) r = fmaxf(r, __shfl_xor_sync(0xffffffffu, r, o));
        if (threadIdx.x == 0) red[0] = r;
    }
    __syncthreads();
    float out = red[0];
    __syncthreads();
    return out;
}

__device__ __forceinline__ float blockReduceSum256(float v, float* red) {
    #pragma unroll
    for (int o = 16; o; o >>= 1) v += __shfl_xor_sync(0xffffffffu, v, o);
    if ((threadIdx.x & 31) == 0) red[threadIdx.x >> 5] = v;
    __syncthreads();
    if (threadIdx.x < 32) {
        float r = (threadIdx.x < 8) ? red[threadIdx.x] : 0.f;
        #pragma unroll
        for (int o = 4; o; o >>= 1) r += __shfl_xor_sync(0xffffffffu, r, o);
        if (threadIdx.x == 0) red[0] = r;
    }
    __syncthreads();
    float out = red[0];
    __syncthreads();
    return out;
}

// ---------------- single merged fp32->bf16 convert (9 segments) ----------------
#define SEG0 (C3H * CE / 4)
#define SEG1 (SEG0 + C3H * CH / 4)
#define SEG2 (SEG1 + CH * CM / 4)
#define SEG3 (SEG2 + CH * CM / 4)
#define SEG4 (SEG3 + CH * CM2 / 4)
#define SEG5 (SEG4 + (size_t)CV * CF / 4)
#define SEG6 (SEG5 + CB * CS * CM / 4)
#define SEG7 (SEG6 + CB * CU * CM / 4)
#define SEG8 (SEG7 + CB * CW * CM2 / 4)

__global__ void convert_all_kernel(
    const float* __restrict__ s0, const float* __restrict__ s1,
    const float* __restrict__ s2, const float* __restrict__ s3,
    const float* __restrict__ s4, const float* __restrict__ s5,
    const float* __restrict__ s6, const float* __restrict__ s7,
    const float* __restrict__ s8)
{
    size_t i4 = (size_t)blockIdx.x * 256 + threadIdx.x;
    const float* src; __nv_bfloat16* dst; size_t off;
    if      (i4 < SEG0) { src = s0; dst = gb_Wih0; off = i4; }
    else if (i4 < SEG1) { src = s1; dst = gb_Wih1; off = i4 - SEG0; }
    else if (i4 < SEG2) { src = s2; dst = gb_atts; off = i4 - SEG1; }
    else if (i4 < SEG3) { src = s3; dst = gb_attu; off = i4 - SEG2; }
    else if (i4 < SEG4) { src = s4; dst = gb_attw; off = i4 - SEG3; }
    else if (i4 < SEG5) { src = s5; dst = gb_outw; off = i4 - SEG4; }
    else if (i4 < SEG6) { src = s6; dst = gb_sout; off = i4 - SEG5; }
    else if (i4 < SEG7) { src = s7; dst = gb_uout; off = i4 - SEG6; }
    else if (i4 < SEG8) { src = s8; dst = gb_wout; off = i4 - SEG7; }
    else return;
    float4 v = ((const float4*)src)[off];
    __nv_bfloat162* d = (__nv_bfloat162*)(dst + off * 4);
    d[0] = __floats2bfloat162_rn(v.x, v.y);
    d[1] = __floats2bfloat162_rn(v.z, v.w);
}

// ---------------- embedding gather ----------------
__global__ void embed_kernel(const int* __restrict__ target, const float* __restrict__ emb) {
    int i = blockIdx.x * blockDim.x + threadIdx.x;
    if (i < CB * CT * CE) {
        int bt = i / CE, e = i - bt * CE;
        gb_emb[i] = __float2bfloat16(emb[(size_t)target[bt] * CE + e]);
    }
}

// ---------------- mma / ldmatrix / cp.async helpers ----------------
__device__ __forceinline__ void mma_bf16(float* d, const unsigned* a, const unsigned* b) {
    asm volatile(
        "mma.sync.aligned.m16n8k16.row.col.f32.bf16.bf16.f32 "
        "{%0,%1,%2,%3}, {%4,%5,%6,%7}, {%8,%9}, {%0,%1,%2,%3};"
        : "+f"(d[0]), "+f"(d[1]), "+f"(d[2]), "+f"(d[3])
        : "r"(a[0]), "r"(a[1]), "r"(a[2]), "r"(a[3]), "r"(b[0]), "r"(b[1]));
}

__device__ __forceinline__ void ldsm4(unsigned& r0, unsigned& r1, unsigned& r2, unsigned& r3,
                                      unsigned addr) {
    asm volatile("ldmatrix.sync.aligned.m8n8.x4.shared.b16 {%0,%1,%2,%3}, [%4];"
        : "=r"(r0), "=r"(r1), "=r"(r2), "=r"(r3) : "r"(addr));
}

// NON-trans x2: B tile stored [n rows][k cols] (K-contiguous) -> fragment
// B[k][n] with n = lane>>2, k = (lane&3)*2 — matches mma m16n8k16 row.col.
// (R8 bug: used .trans here, which delivers the k/n-swapped fragment.)
__device__ __forceinline__ void ldsm2(unsigned& r0, unsigned& r1, unsigned addr) {
    asm volatile("ldmatrix.sync.aligned.m8n8.x2.shared.b16 {%0,%1}, [%2];"
        : "=r"(r0), "=r"(r1) : "r"(addr));
}

__device__ __forceinline__ void cpa16(unsigned dst, const void* src) {
    asm volatile("cp.async.ca.shared.global [%0], [%1], 16;" :: "r"(dst), "l"(src));
}

// ---------------- bf16 tensor-core NT GEMM, 3-stage cp.async + ldmatrix ----------------
template<bool OB>
__global__ __launch_bounds__(256, 2) void bgemm_nt(
    const __nv_bfloat16* __restrict__ A, const __nv_bfloat16* __restrict__ Bm,
    const float* __restrict__ bias, void* __restrict__ Cv,
    int K, int lda, int ldb, int ldc, long sA, long sB, long sC)
{
    __shared__ unsigned As[3][2048];
    __shared__ unsigned Bs[3][2048];
    const __nv_bfloat16* Ab = A + (size_t)blockIdx.z * sA + (size_t)(blockIdx.x * 128) * lda;
    const __nv_bfloat16* Bb = Bm + (size_t)blockIdx.z * sB + (size_t)(blockIdx.y * 128) * ldb;
    int tid = threadIdx.x;
    int warp = tid >> 5, lane = tid & 31;
    int wm = (warp >> 2) * 64, wn = (warp & 3) * 32;
    int lr = lane >> 2, lq = lane & 3;

    int r0 = tid >> 2, g0 = tid & 3;
    unsigned woff = (unsigned)(r0 * 64 + ((g0 ^ ((r0 >> 1) & 3)) << 4));
    unsigned baseA = (unsigned)__cvta_generic_to_shared(&As[0][0]);
    unsigned baseB = (unsigned)__cvta_generic_to_shared(&Bs[0][0]);
    const __nv_bfloat16* srcA0 = Ab + (size_t)r0 * lda + g0 * 8;
    const __nv_bfloat16* srcA1 = srcA0 + (size_t)64 * lda;
    const __nv_bfloat16* srcB0 = Bb + (size_t)r0 * ldb + g0 * 8;
    const __nv_bfloat16* srcB1 = srcB0 + (size_t)64 * ldb;

    int lt = lane >> 3, rr = lane & 7;
    int gAoff = lt >> 1;
    unsigned rowA64[4]; unsigned swzA[4];
    #pragma unroll
    for (int mi = 0; mi < 4; mi++) {
        int row = wm + mi * 16 + ((lt & 1) << 3) + rr;
        rowA64[mi] = row * 64;
        swzA[mi] = (row >> 1) & 3;
    }
    int gBoff = lt & 1;
    unsigned rowB64[2]; unsigned swzB[2];
    #pragma unroll
    for (int np = 0; np < 2; np++) {
        int row = wn + np * 16 + ((lt >> 1) << 3) + rr;
        rowB64[np] = row * 64;
        swzB[np] = (row >> 1) & 3;
    }

    float acc[4][4][4];
    #pragma unroll
    for (int mi = 0; mi < 4; mi++)
        #pragma unroll
        for (int ni = 0; ni < 4; ni++)
            #pragma unroll
            for (int r = 0; r < 4; r++) acc[mi][ni][r] = 0.f;

#define STAGE_LOAD(st, kt) do { \
        cpa16(baseA + (st) * 8192 + woff, srcA0 + (kt)); \
        cpa16(baseA + (st) * 8192 + woff + 4096, srcA1 + (kt)); \
        cpa16(baseB + (st) * 8192 + woff, srcB0 + (kt)); \
        cpa16(baseB + (st) * 8192 + woff + 4096, srcB1 + (kt)); \
        asm volatile("cp.async.commit_group;"); } while (0)

    int nt = K / 32;
    STAGE_LOAD(0, 0);
    STAGE_LOAD(1, 32);

    for (int it = 0; it < nt; it++) {
        if (it + 1 < nt) asm volatile("cp.async.wait_group 1;");
        else             asm volatile("cp.async.wait_group 0;");
        __syncthreads();
        if (it + 2 < nt) STAGE_LOAD((it + 2) % 3, (it + 2) * 32);

        int s = it % 3;
        unsigned stA = baseA + s * 8192;
        unsigned stB = baseB + s * 8192;
        #pragma unroll
        for (int ks = 0; ks < 2; ks++) {
            const int kg = ks * 2;
            unsigned a[4][4], b[4][2];
            #pragma unroll
            for (int mi = 0; mi < 4; mi++)
                ldsm4(a[mi][0], a[mi][1], a[mi][2], a[mi][3],
                      stA + rowA64[mi] + ((unsigned)((kg + gAoff) ^ swzA[mi]) << 4));
            #pragma unroll
            for (int np = 0; np < 2; np++)
                ldsm4(b[2 * np][0], b[2 * np][1], b[2 * np + 1][0], b[2 * np + 1][1],
                      stB + rowB64[np] + ((unsigned)((kg + gBoff) ^ swzB[np]) << 4));
            #pragma unroll
            for (int mi = 0; mi < 4; mi++)
                #pragma unroll
                for (int ni = 0; ni < 4; ni++)
                    mma_bf16(acc[mi][ni], a[mi], b[ni]);
        }
    }
#undef STAGE_LOAD

    int m0 = blockIdx.x * 128, n0 = blockIdx.y * 128;
    #pragma unroll
    for (int mi = 0; mi < 4; mi++) {
        #pragma unroll
        for (int ni = 0; ni < 4; ni++) {
            int m = m0 + wm + mi * 16 + lr;
            int n = n0 + wn + ni * 8 + lq * 2;
            float b0 = bias ? bias[n] : 0.f;
            float b1 = bias ? bias[n + 1] : 0.f;
            float v00 = acc[mi][ni][0] + b0, v01 = acc[mi][ni][1] + b1;
            float v10 = acc[mi][ni][2] + b0, v11 = acc[mi][ni][3] + b1;
            if (OB) {
                __nv_bfloat16* Cb = (__nv_bfloat16*)Cv + (size_t)blockIdx.z * sC;
                *(__nv_bfloat162*)(Cb + (size_t)m * ldc + n) = __floats2bfloat162_rn(v00, v01);
                *(__nv_bfloat162*)(Cb + (size_t)(m + 8) * ldc + n) = __floats2bfloat162_rn(v10, v11);
            } else {
                float* Cb = (float*)Cv + (size_t)blockIdx.z * sC;
                *(float2*)(Cb + (size_t)m * ldc + n) = make_float2(v00, v01);
                *(float2*)(Cb + (size_t)(m + 8) * ldc + n) = make_float2(v10, v11);
            }
        }
    }
}

// ---------------- tensor-core persistent GRU ----------------
// 32 blocks; block owns 32 hidden units -> 96 Wh rows [r|z|n], resident in smem (bf16).
// Per step: out[96,8] = Wh_tile[96,1024] @ h^T[1024,8] via m16n8k16 (warps 0-5),
// warps 6-7 prefetch gi tile; gate math on 256 threads (fp32, h_prev in-register);
// h broadcast via double-buffered bf16 global + one grid barrier per step.
#define GNB 32
#define GKP 1032   // padded K stride (elems): 2064 B, ≡16 mod 128 -> conflict-free ldmatrix
#define GRU_SMEM (104 * GKP * 2 + 2 * 96 * 9 * 4)

__global__ __launch_bounds__(256) void gru_mma_kernel(
    const float* __restrict__ gi, const float* __restrict__ Wh,
    const float* __restrict__ bh, float* __restrict__ hout,
    __nv_bfloat16* __restrict__ houtb, int ldo)
{
    extern __shared__ __nv_bfloat16 dyn[];
    __nv_bfloat16* whs = dyn;                       // [96][GKP]
    __nv_bfloat16* hs  = dyn + 96 * GKP;            // [8][GKP]   rows = batch, cols = k
    float* gates = (float*)(dyn + 104 * GKP);       // [96][9]
    float* gis   = gates + 96 * 9;                  // [96][9]
    int tid = threadIdx.x, warp = tid >> 5, lane = tid & 31;
    int j0 = blockIdx.x * 32;

    // load Wh tile (fp32 -> bf16), rows: [0,32)=r, [32,64)=z, [64,96)=n
    for (int idx = tid; idx < 96 * CH; idx += 256) {
        int row = idx >> 10, k = idx & (CH - 1);
        int gate = row >> 5, u = row & 31;
        whs[row * GKP + k] = __float2bfloat16(Wh[(size_t)(gate * CH + j0 + u) * CH + k]);
    }
    for (int idx = tid; idx < CB * GKP; idx += 256) hs[idx] = __float2bfloat16(0.f);

    int j = tid & 31, b = tid >> 5;   // this thread's (hidden unit, batch)
    float bhr = bh[j0 + j], bhz = bh[CH + j0 + j], bhn = bh[2 * CH + j0 + j];
    float hprev = 0.f;

    unsigned whb = (unsigned)__cvta_generic_to_shared(whs);
    unsigned hsb = (unsigned)__cvta_generic_to_shared(hs);
    int lt = lane >> 3, rr = lane & 7;
    unsigned aAddr = whb + (unsigned)(((warp << 4) + ((lt & 1) << 3) + rr) * GKP
                                      + ((lt >> 1) << 3)) * 2u;
    int ln = lane & 15;
    unsigned bAddr = hsb + (unsigned)((ln & 7) * GKP + ((ln >> 3) << 3)) * 2u;
    __syncthreads();

    for (int t = 0; t < CT; t++) {
        if (warp < 6) {
            float acc[4][4];
            #pragma unroll
            for (int i = 0; i < 4; i++)
                #pragma unroll
                for (int r = 0; r < 4; r++) acc[i][r] = 0.f;
            #pragma unroll 8
            for (int ks = 0; ks < 64; ks++) {
                unsigned av[4], bv[2];
                ldsm4(av[0], av[1], av[2], av[3], aAddr + ks * 32u);
                ldsm2(bv[0], bv[1], bAddr + ks * 32u);
                mma_bf16(acc[ks & 3], av, bv);
            }
            float c0 = acc[0][0] + acc[1][0] + acc[2][0] + acc[3][0];
            float c1 = acc[0][1] + acc[1][1] + acc[2][1] + acc[3][1];
            float c2 = acc[0][2] + acc[1][2] + acc[2][2] + acc[3][2];
            float c3 = acc[0][3] + acc[1][3] + acc[2][3] + acc[3][3];
            int r_ = lane >> 2, q = lane & 3;
            int rowb = (warp << 4) + r_;
            gates[rowb * 9 + 2 * q]           = c0;
            gates[rowb * 9 + 2 * q + 1]       = c1;
            gates[(rowb + 8) * 9 + 2 * q]     = c2;
            gates[(rowb + 8) * 9 + 2 * q + 1] = c3;
        } else {
            // warps 6,7: prefetch gi tile (96 x 8 values) into smem
            for (int idx = tid - 192; idx < 768; idx += 64) {
                int g = idx >> 8, rem = idx & 255, jj = rem & 31, bb = rem >> 5;
                gis[(g * 32 + jj) * 9 + bb] =
                    gi[(size_t)(bb * CT + t) * C3H + g * CH + j0 + jj];
            }
        }
        __syncthreads();

        float rg = 1.f / (1.f + expf(-(gis[j * 9 + b] + gates[j * 9 + b] + bhr)));
        float zg = 1.f / (1.f + expf(-(gis[(32 + j) * 9 + b] + gates[(32 + j) * 9 + b] + bhz)));
        float ng = tanhf(gis[(64 + j) * 9 + b] + rg * (gates[(64 + j) * 9 + b] + bhn));
        float hn = (1.f - zg) * ng + zg * hprev;
        hprev = hn;
        if (hout) hout[(size_t)(b * CT + t) * CH + j0 + j] = hn;
        houtb[(size_t)(b * CT + t) * ldo + j0 + j] = __float2bfloat16(hn);
        g_hbf[(t + 1) & 1][b * CH + j0 + j] = __float2bfloat16(hn);

        grid_sync_all(GNB);

        // reload full h (bf16) into smem for next step
        const __nv_bfloat16* hb = g_hbf[(t + 1) & 1];
        for (int idx = tid; idx < CB * CH / 8; idx += 256) {
            int bb = idx >> 7, kk = (idx & 127) << 3;
            *(uint4*)(hs + bb * GKP + kk) = *(const uint4*)(hb + bb * CH + kk);
        }
        __syncthreads();
    }
}

// ---------------- small attention scores (one warp per dot) ----------------
__global__ void attn_scores_kernel(const float* __restrict__ q, const float* __restrict__ proj,
                                   float* __restrict__ out, int N) {
    int gw = (blockIdx.x * blockDim.x + threadIdx.x) >> 5;
    int lane = threadIdx.x & 31;
    if (gw >= CB * CT * N) return;
    int n = gw % N;
    int bt = gw / N;
    int b = bt / CT;
    const float* qp = q + (size_t)bt * CH;
    const float* pp = proj + (size_t)(b * N + n) * CH;
    float acc = 0.f;
    for (int k = lane * 4; k < CH; k += 128) {
        float4 qa = *(const float4*)(qp + k);
        float4 pa = *(const float4*)(pp + k);
        acc += qa.x * pa.x + qa.y * pa.y + qa.z * pa.z + qa.w * pa.w;
    }
    #pragma unroll
    for (int o = 16; o; o >>= 1) acc += __shfl_xor_sync(0xffffffffu, acc, o);
    if (lane == 0) out[gw] = acc;
}

// ---------------- fused masked softmaxes + hierarchical combine (bf16 out) ----------------
__global__ __launch_bounds__(256) void combine_kernel(
    const int* __restrict__ s_len, const int* __restrict__ u_len, const int* __restrict__ w_len,
    const int* __restrict__ seg, const int* __restrict__ utt)
{
    int bt = blockIdx.x, b = bt / CT, tid = threadIdx.x;
    __shared__ float ss[CS];
    __shared__ float su[CU];
    __shared__ float sw[CW];
    __shared__ float red[32];
    int sl = s_len[b], ul = u_len[b], wl = w_len[b];

    if (tid < 32) {
        float v = (tid < sl) ? g_sc_s[bt * CS + tid] : -INFINITY;
        float m = v;
        #pragma unroll
        for (int o = 16; o; o >>= 1) m = fmaxf(m, __shfl_xor_sync(0xffffffffu, m, o));
        float e = (tid < sl) ? expf(v - m) : 0.f;
        float s = e;
        #pragma unroll
        for (int o = 16; o; o >>= 1) s += __shfl_xor_sync(0xffffffffu, s, o);
        if (tid < CS) ss[tid] = e / s;
    }
    float uv = (tid < CU && tid < ul) ? g_sc_u[bt * CU + tid] : -INFINITY;
    float um = blockReduceMax256(uv, red);
    float ue = (tid < CU && tid < ul) ? expf(uv - um) : 0.f;
    float us = blockReduceSum256(ue, red);
    if (tid < CU) su[tid] = ue / us;
    float wv[4], we[4];
    float wm = -INFINITY;
    #pragma unroll
    for (int i = 0; i < 4; i++) {
        int idx = tid + 256 * i;
        wv[i] = (idx < wl) ? g_sc_w[(size_t)bt * CW + idx] : -INFINITY;
        wm = fmaxf(wm, wv[i]);
    }
    wm = blockReduceMax256(wm, red);
    float wsum = 0.f;
    #pragma unroll
    for (int i = 0; i < 4; i++) {
        int idx = tid + 256 * i;
        we[i] = (idx < wl) ? expf(wv[i] - wm) : 0.f;
        wsum += we[i];
    }
    wsum = blockReduceSum256(wsum, red);
    #pragma unroll
    for (int i = 0; i < 4; i++) sw[tid + 256 * i] = we[i] / wsum;
    __syncthreads();
    if (tid < CU) {
        float v2 = (tid < ul) ? ss[seg[b * CU + tid]] * su[tid] : 0.f;
        su[tid] = v2;
    }
    __syncthreads();
    float pv[4];
    #pragma unroll
    for (int i = 0; i < 4; i++) {
        int idx = tid + 256 * i;
        pv[i] = (idx < wl) ? su[utt[b * CW + idx]] * sw[idx] : 0.f;
    }
    float pm = fmaxf(fmaxf(pv[0], pv[1]), fmaxf(pv[2], pv[3]));
    pm = blockReduceMax256(pm, red);
    float pe[4];
    float psum = 0.f;
    #pragma unroll
    for (int i = 0; i < 4; i++) { pe[i] = expf(pv[i] - pm); psum += pe[i]; }
    psum = blockReduceSum256(psum, red);
    #pragma unroll
    for (int i = 0; i < 4; i++)
        gb_suw[(size_t)bt * CW + tid + 256 * i] = __float2bfloat16(pe[i] / psum);
}

// ---------------- per-batch transpose of w_output -> bf16 [B,2M,W] ----------------
__global__ void transpose_w_kernel(const float* __restrict__ wo) {
    __shared__ float tile[32][33];
    int b = blockIdx.z;
    int w0 = blockIdx.x * 32, m0 = blockIdx.y * 32;
    int x = threadIdx.x, y = threadIdx.y;
    #pragma unroll
    for (int i = 0; i < 32; i += 8)
        tile[y + i][x] = wo[((size_t)b * CW + (w0 + y + i)) * CM2 + m0 + x];
    __syncthreads();
    #pragma unroll
    for (int i = 0; i < 32; i += 8)
        gb_wT[((size_t)b * CM2 + (m0 + y + i)) * CW + w0 + x] = __float2bfloat16(tile[x][y + i]);
}

// ---------------- in-place log_softmax over V per (b,t) row ----------------
__global__ __launch_bounds__(256) void logsoftmax_kernel(float* __restrict__ out) {
    __shared__ float red[32];
    int row = blockIdx.x, tid = threadIdx.x;
    float* p = out + (size_t)row * CV;
    float m = -INFINITY;
    for (int i = tid; i < CV; i += 256) m = fmaxf(m, p[i]);
    m = blockReduceMax256(m, red);
    float s = 0.f;
    for (int i = tid; i < CV; i += 256) s += expf(p[i] - m);
    s = blockReduceSum256(s, red);
    float lse = m + logf(s);
    for (int i = tid; i < CV; i += 256) p[i] -= lse;
}

// ---------------- launch ----------------
extern "C" void kernel_launch(void* const* d_in, const int* in_sizes, int n_in,
                              void* d_out, int out_size) {
    const int*   target   = (const int*)d_in[0];
    const float* embedding= (const float*)d_in[1];
    const float* W_ih0    = (const float*)d_in[2];
    const float* W_hh0    = (const float*)d_in[3];
    const float* b_ih0    = (const float*)d_in[4];
    const float* b_hh0    = (const float*)d_in[5];
    const float* W_ih1    = (const float*)d_in[6];
    const float* W_hh1    = (const float*)d_in[7];
    const float* b_ih1    = (const float*)d_in[8];
    const float* b_hh1    = (const float*)d_in[9];
    const float* att_s_w  = (const float*)d_in[10];
    const float* att_s_b  = (const float*)d_in[11];
    const float* att_u_w  = (const float*)d_in[12];
    const float* att_u_b  = (const float*)d_in[13];
    const float* att_w_w  = (const float*)d_in[14];
    const float* att_w_b  = (const float*)d_in[15];
    const float* out_w    = (const float*)d_in[16];
    const float* out_b    = (const float*)d_in[17];
    const float* s_output = (const float*)d_in[18];
    const float* u_output = (const float*)d_in[19];
    const float* w_output = (const float*)d_in[20];
    const int*   s_len    = (const int*)d_in[21];
    const int*   u_len    = (const int*)d_in[22];
    const int*   w_len    = (const int*)d_in[23];
    const int*   seg      = (const int*)d_in[24];
    const int*   utt      = (const int*)d_in[25];
    float* out = (float*)d_out;

    float *p_gi, *p_rnn, *p_ps, *p_pu, *p_scs, *p_scu, *p_scw;
    cudaGetSymbolAddress((void**)&p_gi, g_gi);
    cudaGetSymbolAddress((void**)&p_rnn, g_rnn);
    cudaGetSymbolAddress((void**)&p_ps, g_proj_s);
    cudaGetSymbolAddress((void**)&p_pu, g_proj_u);
    cudaGetSymbolAddress((void**)&p_scs, g_sc_s);
    cudaGetSymbolAddress((void**)&p_scu, g_sc_u);
    cudaGetSymbolAddress((void**)&p_scw, g_sc_w);
    __nv_bfloat16 *b_h1, *b_feat, *b_suw, *b_sout, *b_uout, *b_wout,
                  *b_wT, *b_pw, *b_Wih0, *b_Wih1, *b_atts, *b_attu, *b_attw, *b_outw, *b_emb;
    cudaGetSymbolAddress((void**)&b_emb, gb_emb);
    cudaGetSymbolAddress((void**)&b_h1, gb_h1);
    cudaGetSymbolAddress((void**)&b_feat, gb_feat);
    cudaGetSymbolAddress((void**)&b_suw, gb_suw);
    cudaGetSymbolAddress((void**)&b_sout, gb_sout);
    cudaGetSymbolAddress((void**)&b_uout, gb_uout);
    cudaGetSymbolAddress((void**)&b_wout, gb_wout);
    cudaGetSymbolAddress((void**)&b_wT, gb_wT);
    cudaGetSymbolAddress((void**)&b_pw, gb_pw);
    cudaGetSymbolAddress((void**)&b_Wih0, gb_Wih0);
    cudaGetSymbolAddress((void**)&b_Wih1, gb_Wih1);
    cudaGetSymbolAddress((void**)&b_atts, gb_atts);
    cudaGetSymbolAddress((void**)&b_attu, gb_attu);
    cudaGetSymbolAddress((void**)&b_attw, gb_attw);
    cudaGetSymbolAddress((void**)&b_outw, gb_outw);

    cudaFuncSetAttribute(gru_mma_kernel,
                         cudaFuncAttributeMaxDynamicSharedMemorySize, GRU_SMEM);

    // 1. merged fp32->bf16 conversions
    convert_all_kernel<<<(unsigned)(SEG8 / 256), 256>>>(
        W_ih0, W_ih1, att_s_w, att_u_w, att_w_w, out_w, s_output, u_output, w_output);
    // 2. embedding gather
    embed_kernel<<<(CB * CT * CE + 255) / 256, 256>>>(target, embedding);
    // 3. proj_w (independent of GRU; placed early for ncu capture alignment)
    bgemm_nt<true><<<dim3((CB * CW) / 128, CH / 128, 1), 256>>>(b_wout, b_attw, att_w_b, b_pw,
        CM2, CM2, CM2, CH, 0, 0, 0);
    // 4. gi0 = emb @ W_ih0^T + b_ih0
    bgemm_nt<false><<<dim3((CB * CT) / 128, C3H / 128, 1), 256>>>(b_emb, b_Wih0, b_ih0, p_gi,
        CE, CE, CE, C3H, 0, 0, 0);
    // 5. GRU layer 0 (tensor-core persistent) -> bf16 gb_h1
    gru_mma_kernel<<<GNB, 256, GRU_SMEM>>>(p_gi, W_hh0, b_hh0, nullptr, b_h1, CH);
    // 6. gi1 = h1 @ W_ih1^T + b_ih1
    bgemm_nt<false><<<dim3((CB * CT) / 128, C3H / 128, 1), 256>>>(b_h1, b_Wih1, b_ih1, p_gi,
        CH, CH, CH, C3H, 0, 0, 0);
    // 7. GRU layer 1 -> fp32 rnn + bf16 directly into feat[:, 1024:]
    gru_mma_kernel<<<GNB, 256, GRU_SMEM>>>(p_gi, W_hh1, b_hh1, p_rnn, b_feat + CM2, CF);
    // 8. remaining attention projections
    bgemm_nt<false><<<dim3((CB * CS) / 128, CH / 128, 1), 256>>>(b_sout, b_atts, att_s_b, p_ps,
        CM, CM, CM, CH, 0, 0, 0);
    bgemm_nt<false><<<dim3((CB * CU) / 128, CH / 128, 1), 256>>>(b_uout, b_attu, att_u_b, p_pu,
        CM, CM, CM, CH, 0, 0, 0);
    // 9. raw scores
    attn_scores_kernel<<<(CB * CT * CS) / 8, 256>>>(p_rnn, p_ps, p_scs, CS);
    attn_scores_kernel<<<(CB * CT * CU) / 8, 256>>>(p_rnn, p_pu, p_scu, CU);
    bgemm_nt<false><<<dim3(CT / 128, CW / 128, CB), 256>>>(b_feat + CM2, b_pw, nullptr, p_scw,
        CH, CF, CH, CW, (long)CT * CF, (long)CW * CH, (long)CT * CW);
    // 10. masked softmaxes + hierarchical combine + final softmax
    combine_kernel<<<CB * CT, 256>>>(s_len, u_len, w_len, seg, utt);
    // 11. context = suw @ w_output -> bf16 feat[:, :1024]
    transpose_w_kernel<<<dim3(CW / 32, CM2 / 32, CB), dim3(32, 8)>>>(w_output);
    bgemm_nt<true><<<dim3(CT / 128, CM2 / 128, CB), 256>>>(b_suw, b_wT, nullptr, b_feat,
        CW, CW, CW, CF, (long)CT * CW, (long)CM2 * CW, (long)CT * CF);
    // 12. logits = feat @ out_w^T + out_b -> d_out (fp32)
    bgemm_nt<false><<<dim3((CB * CT) / 128, CV / 128, 1), 256>>>(b_feat, b_outw, out_b, out,
        CF, CF, CF, CV, 0, 0, 0);
    // 13. in-place log_softmax
    logsoftmax_kernel<<<CB * CT, 256>>>(out);
}